// round 5
// baseline (speedup 1.0000x reference)
#include <cuda_runtime.h>
#include <cuda_bf16.h>

typedef unsigned int u32; typedef unsigned short u16;
#define NTHR 256

// bf16 hi/lo transposed weight images, built by prep_kernel each launch.
__device__ __align__(16) unsigned char g_wimg[509952];

__device__ __forceinline__ u32 smaddr(const void* p) {
    u32 a; asm("{ .reg .u64 t; cvta.to.shared.u64 t, %1; cvt.u32.u64 %0, t; }" : "=r"(a) : "l"(p));
    return a;
}
__device__ __forceinline__ void ldmx4(u32& r0, u32& r1, u32& r2, u32& r3, u32 a) {
    asm volatile("ldmatrix.sync.aligned.m8n8.x4.shared.b16 {%0,%1,%2,%3}, [%4];"
                 : "=r"(r0), "=r"(r1), "=r"(r2), "=r"(r3) : "r"(a));
}
__device__ __forceinline__ void mma16816(float* c, const u32* a, u32 b0, u32 b1) {
    asm volatile("mma.sync.aligned.m16n8k16.row.col.f32.bf16.bf16.f32 "
                 "{%0,%1,%2,%3},{%4,%5,%6,%7},{%8,%9},{%0,%1,%2,%3};"
                 : "+f"(c[0]), "+f"(c[1]), "+f"(c[2]), "+f"(c[3])
                 : "r"(a[0]), "r"(a[1]), "r"(a[2]), "r"(a[3]), "r"(b0), "r"(b1));
}
__device__ __forceinline__ void cpa16(u32 d, const void* s) {
    asm volatile("cp.async.cg.shared.global [%0], [%1], 16;" :: "r"(d), "l"(s) : "memory");
}
#define CPC() asm volatile("cp.async.commit_group;" ::: "memory")
#define CPW() asm volatile("cp.async.wait_group 0;" ::: "memory")

__device__ __forceinline__ u32 pk(float lo, float hi) {
    u32 r; asm("cvt.rn.bf16x2.f32 %0, %1, %2;" : "=r"(r) : "f"(hi), "f"(lo)); return r;
}
__device__ __forceinline__ void split2(float f0, float f1, u32& h, u32& l) {
    h = pk(f0, f1);
    float h0 = __uint_as_float(h << 16);
    float h1 = __uint_as_float(h & 0xffff0000u);
    l = pk(f0 - h0, f1 - h1);
}

__device__ __forceinline__ void copy_async(u32 dst, const unsigned char* src, int bytes, int tid) {
    for (int i = tid * 16; i < bytes; i += NTHR * 16) cpa16(dst + (u32)i, src + i);
    CPC();
}

// GEMM layer: M=128 (8 warps x 16 rows), N = NT2*16, K = (MF+EF)*16.
// 3 logical bf16 passes (AhWh + AlWh + AhWl) fused so each Wh fragment is
// loaded ONCE and reused by the Ah and Al passes. N-tiles processed in pairs
// to keep C-accumulator RAW distance at 4 mmas.
template <int MF, int EF, int NT2>
__device__ __forceinline__ void gemm_layer(
    float (&C)[16][4],
    const u32 (&AH)[8][4], const u32 (&AL)[8][4],
    const u32 (&XH)[3][4], const u32 (&XL)[3][4],
    u32 wb, u32 halfB, u32 strideEl, u32 thoff)
{
#pragma unroll
    for (int t = 0; t < NT2 * 2; t++) { C[t][0] = 0.f; C[t][1] = 0.f; C[t][2] = 0.f; C[t][3] = 0.f; }
    const u32 rowstep = strideEl * 32u;   // bytes per 16 N-rows
    const u32 base = wb + thoff;
#pragma unroll
    for (int kf = 0; kf < MF + EF; kf++) {
        u32 aH[4], aL[4];
#pragma unroll
        for (int q = 0; q < 4; q++) {
            aH[q] = (kf < MF) ? AH[kf][q] : XH[kf - MF][q];
            aL[q] = (kf < MF) ? AL[kf][q] : XL[kf - MF][q];
        }
        u32 ad = base + (u32)kf * 32u;
#pragma unroll
        for (int pp = 0; pp < NT2 / 2; pp++) {
            u32 h0,h1,h2,h3, g0,g1,g2,g3, l0,l1,l2,l3, m0,m1,m2,m3;
            ldmx4(h0,h1,h2,h3, ad);
            ldmx4(g0,g1,g2,g3, ad + rowstep);
            ldmx4(l0,l1,l2,l3, ad + halfB);
            ldmx4(m0,m1,m2,m3, ad + halfB + rowstep);
            mma16816(C[4*pp+0], aH, h0, h1);
            mma16816(C[4*pp+1], aH, h2, h3);
            mma16816(C[4*pp+2], aH, g0, g1);
            mma16816(C[4*pp+3], aH, g2, g3);
            mma16816(C[4*pp+0], aL, h0, h1);
            mma16816(C[4*pp+1], aL, h2, h3);
            mma16816(C[4*pp+2], aL, g0, g1);
            mma16816(C[4*pp+3], aL, g2, g3);
            mma16816(C[4*pp+0], aH, l0, l1);
            mma16816(C[4*pp+1], aH, l2, l3);
            mma16816(C[4*pp+2], aH, m0, m1);
            mma16816(C[4*pp+3], aH, m2, m3);
            ad += 2u * rowstep;
        }
    }
}

// standard epilogue: C + bias (+relu) -> split into next-layer A frags
template <bool RELU>
__device__ __forceinline__ void epi_std(float (&C)[16][4], u32 (&AH)[8][4], u32 (&AL)[8][4],
                                        const float* bias, int c0)
{
#pragma unroll
    for (int j = 0; j < 8; j++) {
        float2 bA = *(const float2*)(bias + 16 * j + c0);
        float2 bB = *(const float2*)(bias + 16 * j + 8 + c0);
        float f0 = C[2*j][0] + bA.x, f1 = C[2*j][1] + bA.y;
        float f2 = C[2*j][2] + bA.x, f3 = C[2*j][3] + bA.y;
        float g0 = C[2*j+1][0] + bB.x, g1 = C[2*j+1][1] + bB.y;
        float g2 = C[2*j+1][2] + bB.x, g3 = C[2*j+1][3] + bB.y;
        if (RELU) {
            f0 = fmaxf(f0, 0.f); f1 = fmaxf(f1, 0.f); f2 = fmaxf(f2, 0.f); f3 = fmaxf(f3, 0.f);
            g0 = fmaxf(g0, 0.f); g1 = fmaxf(g1, 0.f); g2 = fmaxf(g2, 0.f); g3 = fmaxf(g3, 0.f);
        }
        split2(f0, f1, AH[j][0], AL[j][0]);
        split2(f2, f3, AH[j][1], AL[j][1]);
        split2(g0, g1, AH[j][2], AL[j][2]);
        split2(g2, g3, AH[j][3], AL[j][3]);
    }
}

// ---- prep: fp32 W[k][n] -> transposed bf16 hi/lo images Wt[n][k] with padding ----
__global__ void prep_kernel(const float* w0, const float* w1, const float* w2, const float* w3,
                            const float* w4, const float* w5, const float* wd, const float* wr1)
{
    const float* srcs[8] = {w0, w1, w2, w3, w4, w5, wd, wr1};
    const int Ks[8]   = {39, 128, 128, 167, 128, 128, 128, 143};
    const int Nn[8]   = {128, 128, 128, 128, 128, 128, 128, 64};
    const int st[8]   = {56, 136, 136, 184, 136, 136, 136, 152};
    const int wst[8]  = {128, 128, 128, 128, 128, 128, 129, 64};
    const int cof[8]  = {0, 0, 0, 0, 0, 0, 1, 0};
    const int off[8]  = {0, 28672, 98304, 167936, 262144, 331776, 401408, 471040};
    const int half[8] = {14336, 34816, 34816, 47104, 34816, 34816, 34816, 19456};
    int j = blockIdx.x;
    const float* src = srcs[j];
    int N = Nn[j], S = st[j], tot = N * S;
    for (int idx = threadIdx.x; idx < tot; idx += blockDim.x) {
        int n = idx / S, k = idx - n * S;
        float v = (k < Ks[j]) ? __ldg(src + (size_t)k * wst[j] + cof[j] + n) : 0.f;
        __nv_bfloat16 bh = __float2bfloat16(v);
        __nv_bfloat16 bl = __float2bfloat16(v - __bfloat162float(bh));
        *(u16*)(g_wimg + off[j] + (size_t)idx * 2)           = __bfloat16_as_ushort(bh);
        *(u16*)(g_wimg + off[j] + half[j] + (size_t)idx * 2) = __bfloat16_as_ushort(bl);
    }
}

__global__ void __launch_bounds__(NTHR, 1) nerf_mma_kernel(
    const float* __restrict__ pts, const float* __restrict__ dirs,
    const float* __restrict__ b0, const float* __restrict__ b1,
    const float* __restrict__ b2, const float* __restrict__ b3,
    const float* __restrict__ b4, const float* __restrict__ b5,
    const float* __restrict__ bd, const float* __restrict__ br1,
    const float* __restrict__ wd, const float* __restrict__ wr2,
    const float* __restrict__ br2, float* __restrict__ out, int ntiles)
{
    extern __shared__ __align__(16) unsigned char sm[];
    unsigned char* wbuf0 = sm;                       // 94208
    unsigned char* wbuf1 = sm + 94208;               // 94208
    float* esm  = (float*)(sm + 188416);             // 128 x 48 fp32 embed
    float* aux  = (float*)(sm + 188416 + 24576);
    float* biasS = aux;                              // 8 x 128
    float* wcS   = aux + 1024;                       // wd col 0 (128)
    float* wr2S  = aux + 1152;                       // 64 x 3
    float* br2S  = aux + 1344;                       // 3
    const u32 wb0 = smaddr(wbuf0), wb1 = smaddr(wbuf1);

    const int tid = threadIdx.x, lane = tid & 31, wid = tid >> 5;
    const int c0 = 2 * (lane & 3);
    const int r0 = 16 * wid + (lane >> 2);
    const int nadd = ((lane >> 4) << 3) + (lane & 7);     // ldmatrix row-within-pair
    const int kadd = ((lane >> 3) & 1) << 3;              // ldmatrix k-half

    // stage biases / head weights (once)
    {
        const float* bp[8] = {b0, b1, b2, b3, b4, b5, bd + 1, br1};
#pragma unroll 1
        for (int l = 0; l < 8; l++) {
            int n = (l == 7) ? 64 : 128;
            for (int i = tid; i < n; i += NTHR) biasS[l * 128 + i] = __ldg(bp[l] + i);
        }
        for (int i = tid; i < 128; i += NTHR) wcS[i] = __ldg(wd + (size_t)i * 129);
        for (int i = tid; i < 192; i += NTHR) wr2S[i] = __ldg(wr2 + i);
        if (tid < 3) br2S[tid] = __ldg(br2 + tid);
    }
    // prologue: L0 weights -> wbuf0
    copy_async(wb0, g_wimg, 28672, tid);
    CPW();
    __syncthreads();

    float C[16][4];
    u32 AH[8][4], AL[8][4], XH[3][4], XL[3][4];
    const float bd0 = __ldg(bd);
    const long long NPTS = (long long)ntiles * 128;

    for (int tile = blockIdx.x; tile < ntiles; tile += gridDim.x) {
        // ---- xyz harmonic embed into smem: 2 threads per point ----
        {
            int p = tid & 127, half = tid >> 7;
            const float* q = pts + ((long long)tile * 128 + p) * 3;
            float v0 = __ldg(q), v1 = __ldg(q + 1), v2 = __ldg(q + 2);
            float* er = esm + p * 48;
            if (half == 0) {
                float fr = 1.f;
#pragma unroll
                for (int f = 0; f < 6; f++) {
                    float s, c; sincosf(v0 * fr, &s, &c);
                    er[f] = s; er[18 + f] = c; fr *= 2.f;
                }
                fr = 1.f;
#pragma unroll
                for (int f = 0; f < 3; f++) {
                    float s, c; sincosf(v2 * fr, &s, &c);
                    er[12 + f] = s; er[30 + f] = c; fr *= 2.f;
                }
                er[36] = v0; er[37] = v1; er[38] = v2;
#pragma unroll
                for (int i = 39; i < 48; i++) er[i] = 0.f;
            } else {
                float fr = 1.f;
#pragma unroll
                for (int f = 0; f < 6; f++) {
                    float s, c; sincosf(v1 * fr, &s, &c);
                    er[6 + f] = s; er[24 + f] = c; fr *= 2.f;
                }
                fr = 8.f;
#pragma unroll
                for (int f = 3; f < 6; f++) {
                    float s, c; sincosf(v2 * fr, &s, &c);
                    er[12 + f] = s; er[30 + f] = c; fr *= 2.f;
                }
            }
        }
        __syncthreads();

        // ---- xyz A-frags (kept until L3) ----
#pragma unroll
        for (int j = 0; j < 3; j++) {
            int kc = 16 * j;
            float2 p00 = *(const float2*)(esm + r0 * 48 + kc + c0);
            float2 p10 = *(const float2*)(esm + (r0 + 8) * 48 + kc + c0);
            float2 p01 = *(const float2*)(esm + r0 * 48 + kc + 8 + c0);
            float2 p11 = *(const float2*)(esm + (r0 + 8) * 48 + kc + 8 + c0);
            split2(p00.x, p00.y, XH[j][0], XL[j][0]);
            split2(p10.x, p10.y, XH[j][1], XL[j][1]);
            split2(p01.x, p01.y, XH[j][2], XL[j][2]);
            split2(p11.x, p11.y, XH[j][3], XL[j][3]);
        }

        // ---- L0 (39->128, xyz only) ----
        copy_async(wb1, g_wimg + 28672, 69632, tid);
        gemm_layer<0, 3, 8>(C, AH, AL, XH, XL, wb0, 14336, 56, (u32)((nadd * 56 + kadd) * 2));
        epi_std<true>(C, AH, AL, biasS, c0);
        CPW(); __syncthreads();

        // ---- L1 ----
        copy_async(wb0, g_wimg + 98304, 69632, tid);
        gemm_layer<8, 0, 8>(C, AH, AL, XH, XL, wb1, 34816, 136, (u32)((nadd * 136 + kadd) * 2));
        epi_std<true>(C, AH, AL, biasS + 128, c0);
        CPW(); __syncthreads();

        // ---- L2 ----
        copy_async(wb1, g_wimg + 167936, 94208, tid);
        gemm_layer<8, 0, 8>(C, AH, AL, XH, XL, wb0, 34816, 136, (u32)((nadd * 136 + kadd) * 2));
        epi_std<true>(C, AH, AL, biasS + 256, c0);
        CPW(); __syncthreads();

        // ---- L3 (skip: concat(y, xyz), K=176) ----
        copy_async(wb0, g_wimg + 262144, 69632, tid);
        gemm_layer<8, 3, 8>(C, AH, AL, XH, XL, wb1, 47104, 184, (u32)((nadd * 184 + kadd) * 2));
        epi_std<true>(C, AH, AL, biasS + 384, c0);
        CPW(); __syncthreads();

        // ---- L4 ----
        copy_async(wb1, g_wimg + 331776, 69632, tid);
        gemm_layer<8, 0, 8>(C, AH, AL, XH, XL, wb0, 34816, 136, (u32)((nadd * 136 + kadd) * 2));
        epi_std<true>(C, AH, AL, biasS + 512, c0);
        CPW(); __syncthreads();

        // ---- L5 (+fused density head) ----
        copy_async(wb0, g_wimg + 401408, 69632, tid);
        gemm_layer<8, 0, 8>(C, AH, AL, XH, XL, wb1, 34816, 136, (u32)((nadd * 136 + kadd) * 2));
        {
            const float* bias = biasS + 640;
            float d0 = 0.f, d1 = 0.f;
#pragma unroll
            for (int j = 0; j < 8; j++) {
                float2 bA = *(const float2*)(bias + 16 * j + c0);
                float2 bB = *(const float2*)(bias + 16 * j + 8 + c0);
                float2 wA = *(const float2*)(wcS + 16 * j + c0);
                float2 wB = *(const float2*)(wcS + 16 * j + 8 + c0);
                float f0 = fmaxf(C[2*j][0] + bA.x, 0.f), f1 = fmaxf(C[2*j][1] + bA.y, 0.f);
                float f2 = fmaxf(C[2*j][2] + bA.x, 0.f), f3 = fmaxf(C[2*j][3] + bA.y, 0.f);
                float g0 = fmaxf(C[2*j+1][0] + bB.x, 0.f), g1 = fmaxf(C[2*j+1][1] + bB.y, 0.f);
                float g2 = fmaxf(C[2*j+1][2] + bB.x, 0.f), g3 = fmaxf(C[2*j+1][3] + bB.y, 0.f);
                d0 += f0 * wA.x + f1 * wA.y + g0 * wB.x + g1 * wB.y;
                d1 += f2 * wA.x + f3 * wA.y + g2 * wB.x + g3 * wB.y;
                split2(f0, f1, AH[j][0], AL[j][0]);
                split2(f2, f3, AH[j][1], AL[j][1]);
                split2(g0, g1, AH[j][2], AL[j][2]);
                split2(g2, g3, AH[j][3], AL[j][3]);
            }
            d0 += __shfl_xor_sync(0xffffffffu, d0, 1); d0 += __shfl_xor_sync(0xffffffffu, d0, 2);
            d1 += __shfl_xor_sync(0xffffffffu, d1, 1); d1 += __shfl_xor_sync(0xffffffffu, d1, 2);
            if ((lane & 3) == 0) {
                long long base = (long long)tile * 128;
                out[base + r0]     = fmaxf(d0 + bd0, 0.f);
                out[base + r0 + 8] = fmaxf(d1 + bd0, 0.f);
            }
        }
        CPW(); __syncthreads();

        // ---- L6 (wd cols 1..128, NO relu) ----
        copy_async(wb1, g_wimg + 471040, 38912, tid);
        gemm_layer<8, 0, 8>(C, AH, AL, XH, XL, wb0, 34816, 136, (u32)((nadd * 136 + kadd) * 2));
        epi_std<false>(C, AH, AL, biasS + 768, c0);
        CPW(); __syncthreads();

        // ---- dir embed frag -> XH[0]/XL[0] (xyz frags dead after L3) ----
        {
            const float* dp = dirs + (long long)tile * 3;
            float d[16];
#pragma unroll
            for (int c = 0; c < 3; c++) {
                float v = __ldg(dp + c);
                float s0, cc0, s1, cc1;
                sincosf(v, &s0, &cc0); sincosf(2.f * v, &s1, &cc1);
                d[2*c] = s0; d[2*c+1] = s1; d[6+2*c] = cc0; d[7+2*c] = cc1; d[12+c] = v;
            }
            d[15] = 0.f;
            split2(d[c0], d[c0+1], XH[0][0], XL[0][0]);
            XH[0][1] = XH[0][0]; XL[0][1] = XL[0][0];
            split2(d[c0+8], d[c0+9], XH[0][2], XL[0][2]);
            XH[0][3] = XH[0][2]; XL[0][3] = XL[0][2];
        }

        // ---- L7 (wr1: concat(feat, dir) -> 64, +fused rgb head) ----
        copy_async(wb0, g_wimg, 28672, tid);   // next tile's L0
        gemm_layer<8, 1, 4>(C, AH, AL, XH, XL, wb1, 19456, 152, (u32)((nadd * 152 + kadd) * 2));
        {
            const float* bias = biasS + 896;
            float p00 = 0.f, p01 = 0.f, p02 = 0.f, p10 = 0.f, p11 = 0.f, p12 = 0.f;
#pragma unroll
            for (int j = 0; j < 8; j++) {
                float2 bA = *(const float2*)(bias + 8 * j + c0);
                float f0 = fmaxf(C[j][0] + bA.x, 0.f), f1 = fmaxf(C[j][1] + bA.y, 0.f);
                float f2 = fmaxf(C[j][2] + bA.x, 0.f), f3 = fmaxf(C[j][3] + bA.y, 0.f);
                int n = 8 * j + c0;
                const float* wA = wr2S + n * 3;
                const float* wB = wr2S + (n + 1) * 3;
                p00 += f0 * wA[0] + f1 * wB[0];
                p01 += f0 * wA[1] + f1 * wB[1];
                p02 += f0 * wA[2] + f1 * wB[2];
                p10 += f2 * wA[0] + f3 * wB[0];
                p11 += f2 * wA[1] + f3 * wB[1];
                p12 += f2 * wA[2] + f3 * wB[2];
            }
            p00 += __shfl_xor_sync(0xffffffffu, p00, 1); p00 += __shfl_xor_sync(0xffffffffu, p00, 2);
            p01 += __shfl_xor_sync(0xffffffffu, p01, 1); p01 += __shfl_xor_sync(0xffffffffu, p01, 2);
            p02 += __shfl_xor_sync(0xffffffffu, p02, 1); p02 += __shfl_xor_sync(0xffffffffu, p02, 2);
            p10 += __shfl_xor_sync(0xffffffffu, p10, 1); p10 += __shfl_xor_sync(0xffffffffu, p10, 2);
            p11 += __shfl_xor_sync(0xffffffffu, p11, 1); p11 += __shfl_xor_sync(0xffffffffu, p11, 2);
            p12 += __shfl_xor_sync(0xffffffffu, p12, 1); p12 += __shfl_xor_sync(0xffffffffu, p12, 2);
            if ((lane & 3) == 0) {
                long long pb = (long long)tile * 128;
                long long o0 = NPTS + (pb + r0) * 3;
                long long o1 = NPTS + (pb + r0 + 8) * 3;
                out[o0]     = 1.f / (1.f + expf(-(p00 + br2S[0])));
                out[o0 + 1] = 1.f / (1.f + expf(-(p01 + br2S[1])));
                out[o0 + 2] = 1.f / (1.f + expf(-(p02 + br2S[2])));
                out[o1]     = 1.f / (1.f + expf(-(p10 + br2S[0])));
                out[o1 + 1] = 1.f / (1.f + expf(-(p11 + br2S[1])));
                out[o1 + 2] = 1.f / (1.f + expf(-(p12 + br2S[2])));
            }
        }
        CPW(); __syncthreads();
    }
}

extern "C" void kernel_launch(void* const* d_in, const int* in_sizes, int n_in,
                              void* d_out, int out_size)
{
    const float* pts  = (const float*)d_in[0];
    const float* dirs = (const float*)d_in[1];
    const float *w0 = (const float*)d_in[2],  *b0 = (const float*)d_in[3];
    const float *w1 = (const float*)d_in[4],  *b1 = (const float*)d_in[5];
    const float *w2 = (const float*)d_in[6],  *b2 = (const float*)d_in[7];
    const float *w3 = (const float*)d_in[8],  *b3 = (const float*)d_in[9];
    const float *w4 = (const float*)d_in[10], *b4 = (const float*)d_in[11];
    const float *w5 = (const float*)d_in[12], *b5 = (const float*)d_in[13];
    const float *wd = (const float*)d_in[14], *bd = (const float*)d_in[15];
    const float *wr1 = (const float*)d_in[16], *br1 = (const float*)d_in[17];
    const float *wr2 = (const float*)d_in[18], *br2 = (const float*)d_in[19];
    float* out = (float*)d_out;

    int ntiles = in_sizes[1] / 3;   // rays
    int nsm = 0;
    cudaDeviceGetAttribute(&nsm, cudaDevAttrMultiProcessorCount, 0);
    if (nsm <= 0) nsm = 148;
    int grid = nsm < ntiles ? nsm : ntiles;

    size_t smem = 188416 + 24576 + 5392;   // 218384
    cudaFuncSetAttribute(nerf_mma_kernel, cudaFuncAttributeMaxDynamicSharedMemorySize, (int)smem);

    prep_kernel<<<8, 512>>>(w0, w1, w2, w3, w4, w5, wd, wr1);
    nerf_mma_kernel<<<grid, NTHR, smem>>>(pts, dirs, b0, b1, b2, b3, b4, b5,
                                          bd, br1, wd, wr2, br2, out, ntiles);
}

// round 6
// speedup vs baseline: 1.3669x; 1.3669x over previous
#include <cuda_runtime.h>
#include <cuda_bf16.h>

typedef unsigned int u32; typedef unsigned short u16;
#define NTHR 256

// tf32 weight images: transposed Wt[n][k], k-pair interleaved, row-remapped (rho),
// built by prep_kernel each launch.
__device__ __align__(16) unsigned char g_wimg[509952];

__device__ __forceinline__ u32 smaddr(const void* p) {
    u32 a; asm("{ .reg .u64 t; cvta.to.shared.u64 t, %1; cvt.u32.u64 %0, t; }" : "=r"(a) : "l"(p));
    return a;
}
__device__ __forceinline__ u32 cvt_tf32(float f) {
    u32 r; asm("cvt.rna.tf32.f32 %0, %1;" : "=r"(r) : "f"(f)); return r;
}
__device__ __forceinline__ void mma_tf32(float* c, u32 a0, u32 a1, u32 a2, u32 a3, u32 b0, u32 b1) {
    asm volatile("mma.sync.aligned.m16n8k8.row.col.f32.tf32.tf32.f32 "
                 "{%0,%1,%2,%3},{%4,%5,%6,%7},{%8,%9},{%0,%1,%2,%3};"
                 : "+f"(c[0]), "+f"(c[1]), "+f"(c[2]), "+f"(c[3])
                 : "r"(a0), "r"(a1), "r"(a2), "r"(a3), "r"(b0), "r"(b1));
}
__device__ __forceinline__ void cpa16(u32 d, const void* s) {
    asm volatile("cp.async.cg.shared.global [%0], [%1], 16;" :: "r"(d), "l"(s) : "memory");
}
#define CPC() asm volatile("cp.async.commit_group;" ::: "memory")
#define CPW() asm volatile("cp.async.wait_group 0;" ::: "memory")

__device__ __forceinline__ void copy_async(u32 dst, const unsigned char* src, int bytes, int tid) {
    for (int i = tid * 16; i < bytes; i += NTHR * 16) cpa16(dst + (u32)i, src + i);
    CPC();
}

// GEMM layer: M=128 (8 warps x 16 rows), N = NT*8, K = (MF+EF)*8, single-pass tf32.
// AF: chained activation frags (== previous C frags, relabeled via rho in the weight
// image). XF: embed frags. base = smem weight addr incl per-thread offset.
// C accumulator reuse distance = NT mmas (16 for hidden layers).
template <int MF, int EF, int NT, int SB>
__device__ __forceinline__ void gemm_layer(
    float (&C)[16][4], const u32 (&AF)[16][4], const u32 (&XF)[6][4], u32 base)
{
#pragma unroll
    for (int t = 0; t < NT; t++) { C[t][0] = 0.f; C[t][1] = 0.f; C[t][2] = 0.f; C[t][3] = 0.f; }
#pragma unroll
    for (int kf = 0; kf < MF + EF; kf++) {
        u32 a0, a1, a2, a3;
        if (kf < MF) { a0 = AF[kf][0]; a1 = AF[kf][1]; a2 = AF[kf][2]; a3 = AF[kf][3]; }
        else { a0 = XF[kf-MF][0]; a1 = XF[kf-MF][1]; a2 = XF[kf-MF][2]; a3 = XF[kf-MF][3]; }
        u32 ad = base + (u32)kf * 32u;
#pragma unroll
        for (int nt = 0; nt < NT; nt++) {
            u32 b0, b1;
            asm volatile("ld.shared.v2.b32 {%0,%1}, [%2];" : "=r"(b0), "=r"(b1) : "r"(ad));
            mma_tf32(C[nt], a0, a1, a2, a3, b0, b1);
            ad += 8u * SB;
        }
    }
}

// standard epilogue: C + bias (+relu) -> tf32 cvt in place into AF (frag chaining)
template <bool RELU>
__device__ __forceinline__ void epi_std(float (&C)[16][4], u32 (&AF)[16][4],
                                        const float* bias, int q2)
{
#pragma unroll
    for (int nt = 0; nt < 16; nt++) {
        float2 b = *(const float2*)(bias + 8 * nt + q2);
        float f0 = C[nt][0] + b.x, f1 = C[nt][1] + b.y;
        float f2 = C[nt][2] + b.x, f3 = C[nt][3] + b.y;
        if (RELU) {
            f0 = fmaxf(f0, 0.f); f1 = fmaxf(f1, 0.f);
            f2 = fmaxf(f2, 0.f); f3 = fmaxf(f3, 0.f);
        }
        AF[nt][0] = cvt_tf32(f0); AF[nt][1] = cvt_tf32(f2);
        AF[nt][2] = cvt_tf32(f1); AF[nt][3] = cvt_tf32(f3);
    }
}

// ---- prep: fp32 W[k][n] -> tf32 Wt[n][slot], rho-remapped rows, k-pair interleaved ----
__global__ void prep_kernel(const float* w0, const float* w1, const float* w2, const float* w3,
                            const float* w4, const float* w5, const float* wd, const float* wr1)
{
    const float* srcs[8] = {w0, w1, w2, w3, w4, w5, wd, wr1};
    const int Ksrc[8] = {39, 128, 128, 167, 128, 128, 128, 143};
    const int Kslt[8] = {48, 128, 128, 176, 128, 128, 128, 144};
    const int Nn[8]   = {128, 128, 128, 128, 128, 128, 128, 64};
    const int St[8]   = {56, 136, 136, 184, 136, 136, 136, 152};
    const int wst[8]  = {128, 128, 128, 128, 128, 128, 129, 64};
    const int cof[8]  = {0, 0, 0, 0, 0, 0, 1, 0};
    const int off[8]  = {0, 28672, 98304, 167936, 262144, 331776, 401408, 471040};
    const int rmp[8]  = {0, 1, 1, 1, 1, 1, 1, 1};   // remap hidden slots (<128)
    int j = blockIdx.x;
    const float* src = srcs[j];
    int N = Nn[j], S = St[j], KS = Kslt[j], tot = N * KS;
    u32* img = (u32*)(g_wimg + off[j]);
    for (int idx = threadIdx.x; idx < tot; idx += blockDim.x) {
        int n = idx / KS, s = idx - n * KS;
        // source row: rho remap for hidden slots, natural otherwise
        int r = s;
        if (rmp[j] && s < 128) {
            int u = s & 7;
            r = (s & ~7) + ((u < 4) ? 2 * u : 2 * (u - 4) + 1);
        }
        float v = (r < Ksrc[j]) ? __ldg(src + (size_t)r * wst[j] + cof[j] + n) : 0.f;
        u32 tv; asm("cvt.rna.tf32.f32 %0, %1;" : "=r"(tv) : "f"(v));
        // k-pair interleave within each 8-slot group: (k,k+4) adjacent for LDS.64
        int sl = s & 7;
        int posf = (s & ~7) + (sl & 3) * 2 + (sl >> 2);
        img[(size_t)n * S + posf] = tv;
    }
}

#define ESTRIDE 52

__global__ void __launch_bounds__(NTHR, 1) nerf_mma_kernel(
    const float* __restrict__ pts, const float* __restrict__ dirs,
    const float* __restrict__ b0, const float* __restrict__ b1,
    const float* __restrict__ b2, const float* __restrict__ b3,
    const float* __restrict__ b4, const float* __restrict__ b5,
    const float* __restrict__ bd, const float* __restrict__ br1,
    const float* __restrict__ wd, const float* __restrict__ wr2,
    const float* __restrict__ br2, float* __restrict__ out, int ntiles)
{
    extern __shared__ __align__(16) unsigned char sm[];
    unsigned char* wbuf0 = sm;                       // 69632  (even layers)
    unsigned char* wbuf1 = sm + 69632;               // 94208  (odd layers, incl L3)
    float* esm  = (float*)(sm + 163840);             // 128 x ESTRIDE fp32 embed
    float* aux  = (float*)(sm + 163840 + 128 * ESTRIDE * 4);
    float* biasS = aux;                              // 8 x 128
    float* wcS   = aux + 1024;                       // wd col 0 (128)
    float* wr2S  = aux + 1152;                       // 64 x 3
    float* br2S  = aux + 1344;                       // 3
    const u32 wb0 = smaddr(wbuf0), wb1 = smaddr(wbuf1);

    const int tid = threadIdx.x, lane = tid & 31, wid = tid >> 5;
    const int q  = lane & 3;        // quad index
    const int q2 = 2 * q;           // C-frag column offset
    const int r0 = 16 * wid + (lane >> 2);
    const int nl = lane >> 2;       // n-local 0..7

    // stage biases / head weights (once)
    {
        const float* bp[8] = {b0, b1, b2, b3, b4, b5, bd + 1, br1};
#pragma unroll 1
        for (int l = 0; l < 8; l++) {
            int n = (l == 7) ? 64 : 128;
            for (int i = tid; i < n; i += NTHR) biasS[l * 128 + i] = __ldg(bp[l] + i);
        }
        for (int i = tid; i < 128; i += NTHR) wcS[i] = __ldg(wd + (size_t)i * 129);
        for (int i = tid; i < 192; i += NTHR) wr2S[i] = __ldg(wr2 + i);
        if (tid < 3) br2S[tid] = __ldg(br2 + tid);
    }
    // prologue: L0 weights -> wbuf0
    copy_async(wb0, g_wimg, 28672, tid);
    CPW();
    __syncthreads();

    float C[16][4];
    u32 AF[16][4], XF[6][4];
    const float bd0 = __ldg(bd);
    const long long NPTS = (long long)ntiles * 128;

    // per-thread B offsets: n_local * rowbytes + pair offset
    const u32 t224 = (u32)(nl * 224 + q * 8);
    const u32 t544 = (u32)(nl * 544 + q * 8);
    const u32 t736 = (u32)(nl * 736 + q * 8);
    const u32 t608 = (u32)(nl * 608 + q * 8);

    for (int tile = blockIdx.x; tile < ntiles; tile += gridDim.x) {
        // ---- xyz harmonic embed into smem: 2 threads per point ----
        {
            int p = tid & 127, half = tid >> 7;
            const float* qp = pts + ((long long)tile * 128 + p) * 3;
            float v0 = __ldg(qp), v1 = __ldg(qp + 1), v2 = __ldg(qp + 2);
            float* er = esm + p * ESTRIDE;
            if (half == 0) {
                float fr = 1.f;
#pragma unroll
                for (int f = 0; f < 6; f++) {
                    float s, c; sincosf(v0 * fr, &s, &c);
                    er[f] = s; er[18 + f] = c; fr *= 2.f;
                }
                fr = 1.f;
#pragma unroll
                for (int f = 0; f < 3; f++) {
                    float s, c; sincosf(v2 * fr, &s, &c);
                    er[12 + f] = s; er[30 + f] = c; fr *= 2.f;
                }
                er[36] = v0; er[37] = v1; er[38] = v2;
#pragma unroll
                for (int i = 39; i < 48; i++) er[i] = 0.f;
            } else {
                float fr = 1.f;
#pragma unroll
                for (int f = 0; f < 6; f++) {
                    float s, c; sincosf(v1 * fr, &s, &c);
                    er[6 + f] = s; er[24 + f] = c; fr *= 2.f;
                }
                fr = 8.f;
#pragma unroll
                for (int f = 3; f < 6; f++) {
                    float s, c; sincosf(v2 * fr, &s, &c);
                    er[12 + f] = s; er[30 + f] = c; fr *= 2.f;
                }
            }
        }
        __syncthreads();

        // ---- xyz X-frags (natural slot order; kept until L3) ----
#pragma unroll
        for (int f = 0; f < 6; f++) {
            const float* e0 = esm + r0 * ESTRIDE + 8 * f;
            const float* e1 = esm + (r0 + 8) * ESTRIDE + 8 * f;
            XF[f][0] = cvt_tf32(e0[q]);
            XF[f][1] = cvt_tf32(e1[q]);
            XF[f][2] = cvt_tf32(e0[q + 4]);
            XF[f][3] = cvt_tf32(e1[q + 4]);
        }

        // ---- L0 (48 slots, xyz only) ----
        copy_async(wb1, g_wimg + 28672, 69632, tid);
        gemm_layer<0, 6, 16, 224>(C, AF, XF, wb0 + t224);
        epi_std<true>(C, AF, biasS, q2);
        CPW(); __syncthreads();

        // ---- L1 ----
        copy_async(wb0, g_wimg + 98304, 69632, tid);
        gemm_layer<16, 0, 16, 544>(C, AF, XF, wb1 + t544);
        epi_std<true>(C, AF, biasS + 128, q2);
        CPW(); __syncthreads();

        // ---- L2 ----
        copy_async(wb1, g_wimg + 167936, 94208, tid);
        gemm_layer<16, 0, 16, 544>(C, AF, XF, wb0 + t544);
        epi_std<true>(C, AF, biasS + 256, q2);
        CPW(); __syncthreads();

        // ---- L3 (skip: concat(y, xyz), 176 slots) ----
        copy_async(wb0, g_wimg + 262144, 69632, tid);
        gemm_layer<16, 6, 16, 736>(C, AF, XF, wb1 + t736);
        epi_std<true>(C, AF, biasS + 384, q2);
        CPW(); __syncthreads();

        // ---- L4 ----
        copy_async(wb1, g_wimg + 331776, 69632, tid);
        gemm_layer<16, 0, 16, 544>(C, AF, XF, wb0 + t544);
        epi_std<true>(C, AF, biasS + 512, q2);
        CPW(); __syncthreads();

        // ---- L5 (+fused density head) ----
        copy_async(wb0, g_wimg + 401408, 69632, tid);
        gemm_layer<16, 0, 16, 544>(C, AF, XF, wb1 + t544);
        {
            const float* bias = biasS + 640;
            float d0 = 0.f, d1 = 0.f;
#pragma unroll
            for (int nt = 0; nt < 16; nt++) {
                float2 b = *(const float2*)(bias + 8 * nt + q2);
                float2 w = *(const float2*)(wcS + 8 * nt + q2);
                float f0 = fmaxf(C[nt][0] + b.x, 0.f), f1 = fmaxf(C[nt][1] + b.y, 0.f);
                float f2 = fmaxf(C[nt][2] + b.x, 0.f), f3 = fmaxf(C[nt][3] + b.y, 0.f);
                d0 += f0 * w.x + f1 * w.y;
                d1 += f2 * w.x + f3 * w.y;
                AF[nt][0] = cvt_tf32(f0); AF[nt][1] = cvt_tf32(f2);
                AF[nt][2] = cvt_tf32(f1); AF[nt][3] = cvt_tf32(f3);
            }
            d0 += __shfl_xor_sync(0xffffffffu, d0, 1); d0 += __shfl_xor_sync(0xffffffffu, d0, 2);
            d1 += __shfl_xor_sync(0xffffffffu, d1, 1); d1 += __shfl_xor_sync(0xffffffffu, d1, 2);
            if (q == 0) {
                long long base = (long long)tile * 128;
                out[base + r0]     = fmaxf(d0 + bd0, 0.f);
                out[base + r0 + 8] = fmaxf(d1 + bd0, 0.f);
            }
        }
        CPW(); __syncthreads();

        // ---- L6 (wd cols 1..128, NO relu) ----
        copy_async(wb1, g_wimg + 471040, 38912, tid);
        gemm_layer<16, 0, 16, 544>(C, AF, XF, wb0 + t544);
        epi_std<false>(C, AF, biasS + 768, q2);
        CPW(); __syncthreads();

        // ---- dir embed frags -> XF[0..1] (xyz frags dead after L3) ----
        {
            const float* dp = dirs + (long long)tile * 3;
            float d[16];
#pragma unroll
            for (int c = 0; c < 3; c++) {
                float v = __ldg(dp + c);
                float s0, cc0, s1, cc1;
                sincosf(v, &s0, &cc0); sincosf(2.f * v, &s1, &cc1);
                d[2*c] = s0; d[2*c+1] = s1; d[6+2*c] = cc0; d[7+2*c] = cc1; d[12+c] = v;
            }
            d[15] = 0.f;
            XF[0][0] = cvt_tf32(d[q]);      XF[0][1] = XF[0][0];
            XF[0][2] = cvt_tf32(d[4 + q]);  XF[0][3] = XF[0][2];
            XF[1][0] = cvt_tf32(d[8 + q]);  XF[1][1] = XF[1][0];
            XF[1][2] = cvt_tf32(d[12 + q]); XF[1][3] = XF[1][2];
        }

        // ---- L7 (wr1: concat(feat, dir) -> 64, +fused rgb head) ----
        copy_async(wb0, g_wimg, 28672, tid);   // next tile's L0
        gemm_layer<16, 2, 8, 608>(C, AF, XF, wb1 + t608);
        {
            const float* bias = biasS + 896;
            float p00 = 0.f, p01 = 0.f, p02 = 0.f, p10 = 0.f, p11 = 0.f, p12 = 0.f;
#pragma unroll
            for (int nt = 0; nt < 8; nt++) {
                float2 b = *(const float2*)(bias + 8 * nt + q2);
                float f0 = fmaxf(C[nt][0] + b.x, 0.f), f1 = fmaxf(C[nt][1] + b.y, 0.f);
                float f2 = fmaxf(C[nt][2] + b.x, 0.f), f3 = fmaxf(C[nt][3] + b.y, 0.f);
                int p0 = 8 * nt + q2;
                const float* wA = wr2S + p0 * 3;
                const float* wB = wr2S + (p0 + 1) * 3;
                p00 += f0 * wA[0] + f1 * wB[0];
                p01 += f0 * wA[1] + f1 * wB[1];
                p02 += f0 * wA[2] + f1 * wB[2];
                p10 += f2 * wA[0] + f3 * wB[0];
                p11 += f2 * wA[1] + f3 * wB[1];
                p12 += f2 * wA[2] + f3 * wB[2];
            }
            p00 += __shfl_xor_sync(0xffffffffu, p00, 1); p00 += __shfl_xor_sync(0xffffffffu, p00, 2);
            p01 += __shfl_xor_sync(0xffffffffu, p01, 1); p01 += __shfl_xor_sync(0xffffffffu, p01, 2);
            p02 += __shfl_xor_sync(0xffffffffu, p02, 1); p02 += __shfl_xor_sync(0xffffffffu, p02, 2);
            p10 += __shfl_xor_sync(0xffffffffu, p10, 1); p10 += __shfl_xor_sync(0xffffffffu, p10, 2);
            p11 += __shfl_xor_sync(0xffffffffu, p11, 1); p11 += __shfl_xor_sync(0xffffffffu, p11, 2);
            p12 += __shfl_xor_sync(0xffffffffu, p12, 1); p12 += __shfl_xor_sync(0xffffffffu, p12, 2);
            if (q == 0) {
                long long pb = (long long)tile * 128;
                long long o0 = NPTS + (pb + r0) * 3;
                long long o1 = NPTS + (pb + r0 + 8) * 3;
                out[o0]     = 1.f / (1.f + expf(-(p00 + br2S[0])));
                out[o0 + 1] = 1.f / (1.f + expf(-(p01 + br2S[1])));
                out[o0 + 2] = 1.f / (1.f + expf(-(p02 + br2S[2])));
                out[o1]     = 1.f / (1.f + expf(-(p10 + br2S[0])));
                out[o1 + 1] = 1.f / (1.f + expf(-(p11 + br2S[1])));
                out[o1 + 2] = 1.f / (1.f + expf(-(p12 + br2S[2])));
            }
        }
        CPW(); __syncthreads();
    }
}

extern "C" void kernel_launch(void* const* d_in, const int* in_sizes, int n_in,
                              void* d_out, int out_size)
{
    const float* pts  = (const float*)d_in[0];
    const float* dirs = (const float*)d_in[1];
    const float *w0 = (const float*)d_in[2],  *b0 = (const float*)d_in[3];
    const float *w1 = (const float*)d_in[4],  *b1 = (const float*)d_in[5];
    const float *w2 = (const float*)d_in[6],  *b2 = (const float*)d_in[7];
    const float *w3 = (const float*)d_in[8],  *b3 = (const float*)d_in[9];
    const float *w4 = (const float*)d_in[10], *b4 = (const float*)d_in[11];
    const float *w5 = (const float*)d_in[12], *b5 = (const float*)d_in[13];
    const float *wd = (const float*)d_in[14], *bd = (const float*)d_in[15];
    const float *wr1 = (const float*)d_in[16], *br1 = (const float*)d_in[17];
    const float *wr2 = (const float*)d_in[18], *br2 = (const float*)d_in[19];
    float* out = (float*)d_out;

    int ntiles = in_sizes[1] / 3;   // rays
    int nsm = 0;
    cudaDeviceGetAttribute(&nsm, cudaDevAttrMultiProcessorCount, 0);
    if (nsm <= 0) nsm = 148;
    int grid = nsm < ntiles ? nsm : ntiles;

    size_t smem = 163840 + 128 * ESTRIDE * 4 + 5392;   // ~195856
    cudaFuncSetAttribute(nerf_mma_kernel, cudaFuncAttributeMaxDynamicSharedMemorySize, (int)smem);

    prep_kernel<<<8, 512>>>(w0, w1, w2, w3, w4, w5, wd, wr1);
    nerf_mma_kernel<<<grid, NTHR, smem>>>(pts, dirs, b0, b1, b2, b3, b4, b5,
                                          bd, br1, wd, wr2, br2, out, ntiles);
}

// round 7
// speedup vs baseline: 1.4714x; 1.0764x over previous
#include <cuda_runtime.h>
#include <cuda_bf16.h>

typedef unsigned int u32; typedef unsigned short u16;
#define NTHR 256

// tf32 weight images: transposed Wt[n][k], rho-remapped, quad-pair v4 layout,
// built by prep_kernel each launch.
__device__ __align__(16) unsigned char g_wimg[520192];

__device__ __forceinline__ u32 smaddr(const void* p) {
    u32 a; asm("{ .reg .u64 t; cvta.to.shared.u64 t, %1; cvt.u32.u64 %0, t; }" : "=r"(a) : "l"(p));
    return a;
}
__device__ __forceinline__ u32 cvt_tf32(float f) {
    u32 r; asm("cvt.rna.tf32.f32 %0, %1;" : "=r"(r) : "f"(f)); return r;
}
__device__ __forceinline__ void mma_tf32(float* c, const u32* a, u32 b0, u32 b1) {
    asm volatile("mma.sync.aligned.m16n8k8.row.col.f32.tf32.tf32.f32 "
                 "{%0,%1,%2,%3},{%4,%5,%6,%7},{%8,%9},{%0,%1,%2,%3};"
                 : "+f"(c[0]), "+f"(c[1]), "+f"(c[2]), "+f"(c[3])
                 : "r"(a[0]), "r"(a[1]), "r"(a[2]), "r"(a[3]), "r"(b0), "r"(b1));
}
__device__ __forceinline__ void cpa16(u32 d, const void* s) {
    asm volatile("cp.async.cg.shared.global [%0], [%1], 16;" :: "r"(d), "l"(s) : "memory");
}
#define CPC() asm volatile("cp.async.commit_group;" ::: "memory")
#define CPW() asm volatile("cp.async.wait_group 0;" ::: "memory")

__device__ __forceinline__ void copy_async(u32 dst, const unsigned char* src, int bytes, int tid) {
    for (int i = tid * 16; i < bytes; i += NTHR * 16) cpa16(dst + (u32)i, src + i);
    CPC();
}

// GEMM layer: M=128 (8 warps x 16 rows), N = NT*8, K = (MP+XP)*16, single-pass tf32.
// Weight image in quad-pair v4 layout: one ld.shared.v4 per thread feeds 2 mmas
// (k-groups 2g and 2g+1). Per k-pair: 8 batched LDS.128 -> 8 mma (pass A) ->
// 8 mma (pass B). C reuse distance 8.
template <int MP, int XP, int NT, int ST>
__device__ __forceinline__ void gemm_layer(
    float (&C)[16][4], const u32 (&AF)[16][4], const u32 (&XF)[6][4], u32 base)
{
#pragma unroll
    for (int t = 0; t < NT; t++) { C[t][0] = 0.f; C[t][1] = 0.f; C[t][2] = 0.f; C[t][3] = 0.f; }
#pragma unroll
    for (int g = 0; g < MP + XP; g++) {
        u32 aA[4], aB[4];
#pragma unroll
        for (int r = 0; r < 4; r++) {
            aA[r] = (g < MP) ? AF[2 * g][r]     : XF[2 * (g - MP)][r];
            aB[r] = (g < MP) ? AF[2 * g + 1][r] : XF[2 * (g - MP) + 1][r];
        }
        const u32 gaddr = base + (u32)g * 64u;
#pragma unroll
        for (int h = 0; h < NT / 8; h++) {
            u32 V[8][4];
#pragma unroll
            for (int t = 0; t < 8; t++) {
                u32 ad = gaddr + (u32)(8 * h + t) * (8u * (u32)ST);
                asm volatile("ld.shared.v4.b32 {%0,%1,%2,%3}, [%4];"
                    : "=r"(V[t][0]), "=r"(V[t][1]), "=r"(V[t][2]), "=r"(V[t][3]) : "r"(ad));
            }
#pragma unroll
            for (int t = 0; t < 8; t++) mma_tf32(C[8 * h + t], aA, V[t][0], V[t][1]);
#pragma unroll
            for (int t = 0; t < 8; t++) mma_tf32(C[8 * h + t], aB, V[t][2], V[t][3]);
        }
    }
}

// standard epilogue: C + bias (+relu) -> tf32 cvt in place into AF (frag chaining)
template <bool RELU>
__device__ __forceinline__ void epi_std(float (&C)[16][4], u32 (&AF)[16][4],
                                        const float* bias, int q2)
{
#pragma unroll
    for (int nt = 0; nt < 16; nt++) {
        float2 b = *(const float2*)(bias + 8 * nt + q2);
        float f0 = C[nt][0] + b.x, f1 = C[nt][1] + b.y;
        float f2 = C[nt][2] + b.x, f3 = C[nt][3] + b.y;
        if (RELU) {
            f0 = fmaxf(f0, 0.f); f1 = fmaxf(f1, 0.f);
            f2 = fmaxf(f2, 0.f); f3 = fmaxf(f3, 0.f);
        }
        AF[nt][0] = cvt_tf32(f0); AF[nt][1] = cvt_tf32(f2);
        AF[nt][2] = cvt_tf32(f1); AF[nt][3] = cvt_tf32(f3);
    }
}

// ---- prep: fp32 W[k][n] -> tf32 Wt[n][pos], rho-remapped rows, quad-pair v4 layout ----
// Within each 16-slot group: pos = q*4 + j for slot u = q + 4j  ->  one v4 per quad
// holds {k=q, q+4, q+8, q+12} (feeds mma k-groups 2g and 2g+1).
__global__ void prep_kernel(const float* w0, const float* w1, const float* w2, const float* w3,
                            const float* w4, const float* w5, const float* wd, const float* wr1)
{
    const float* srcs[8] = {w0, w1, w2, w3, w4, w5, wd, wr1};
    const int Ksrc[8] = {39, 128, 128, 167, 128, 128, 128, 143};
    const int Kslt[8] = {48, 128, 128, 176, 128, 128, 128, 144};
    const int Nn[8]   = {128, 128, 128, 128, 128, 128, 128, 64};
    const int Sw[8]   = {48, 144, 144, 176, 144, 144, 144, 144};   // row stride in words
    const int wst[8]  = {128, 128, 128, 128, 128, 128, 129, 64};
    const int cof[8]  = {0, 0, 0, 0, 0, 0, 1, 0};
    const int off[8]  = {0, 24576, 98304, 172032, 262144, 335872, 409600, 483328};
    const int rmp[8]  = {0, 1, 1, 1, 1, 1, 1, 1};   // remap hidden slots (<128)
    int j = blockIdx.x;
    const float* src = srcs[j];
    int N = Nn[j], S = Sw[j], KS = Kslt[j], tot = N * KS;
    u32* img = (u32*)(g_wimg + off[j]);
    for (int idx = threadIdx.x; idx < tot; idx += blockDim.x) {
        int n = idx / KS, s = idx - n * KS;
        // source row: rho remap for hidden slots, natural otherwise
        int r = s;
        if (rmp[j] && s < 128) {
            int u = s & 7;
            r = (s & ~7) + ((u < 4) ? 2 * u : 2 * (u - 4) + 1);
        }
        float v = (r < Ksrc[j]) ? __ldg(src + (size_t)r * wst[j] + cof[j] + n) : 0.f;
        u32 tv; asm("cvt.rna.tf32.f32 %0, %1;" : "=r"(tv) : "f"(v));
        // quad-pair v4 position within 16-slot group
        int u16i = s & 15;
        int pos = (s & ~15) + (u16i & 3) * 4 + (u16i >> 2);
        img[(size_t)n * S + pos] = tv;
    }
}

#define ESTRIDE 52

__global__ void __launch_bounds__(NTHR, 1) nerf_mma_kernel(
    const float* __restrict__ pts, const float* __restrict__ dirs,
    const float* __restrict__ b0, const float* __restrict__ b1,
    const float* __restrict__ b2, const float* __restrict__ b3,
    const float* __restrict__ b4, const float* __restrict__ b5,
    const float* __restrict__ bd, const float* __restrict__ br1,
    const float* __restrict__ wd, const float* __restrict__ wr2,
    const float* __restrict__ br2, float* __restrict__ out, int ntiles)
{
    extern __shared__ __align__(16) unsigned char sm[];
    unsigned char* wbuf0 = sm;                       // 73728  (L0/L2/L4/L6)
    unsigned char* wbuf1 = sm + 73728;               // 90112  (L1/L3/L5/L7)
    float* esm  = (float*)(sm + 163840);             // 128 x ESTRIDE fp32 embed
    float* aux  = (float*)(sm + 163840 + 128 * ESTRIDE * 4);
    float* biasS = aux;                              // 8 x 128
    float* wcS   = aux + 1024;                       // wd col 0 (128)
    float* wr2S  = aux + 1152;                       // 64 x 3
    float* br2S  = aux + 1344;                       // 3
    const u32 wb0 = smaddr(wbuf0), wb1 = smaddr(wbuf1);

    const int tid = threadIdx.x, lane = tid & 31, wid = tid >> 5;
    const int q  = lane & 3;        // quad index
    const int q2 = 2 * q;           // C-frag column offset
    const int r0 = 16 * wid + (lane >> 2);
    const int nl = lane >> 2;       // n-local 0..7

    // stage biases / head weights (once)
    {
        const float* bp[8] = {b0, b1, b2, b3, b4, b5, bd + 1, br1};
#pragma unroll 1
        for (int l = 0; l < 8; l++) {
            int n = (l == 7) ? 64 : 128;
            for (int i = tid; i < n; i += NTHR) biasS[l * 128 + i] = __ldg(bp[l] + i);
        }
        for (int i = tid; i < 128; i += NTHR) wcS[i] = __ldg(wd + (size_t)i * 129);
        for (int i = tid; i < 192; i += NTHR) wr2S[i] = __ldg(wr2 + i);
        if (tid < 3) br2S[tid] = __ldg(br2 + tid);
    }
    // prologue: L0 weights -> wbuf0
    copy_async(wb0, g_wimg, 24576, tid);
    CPW();
    __syncthreads();

    float C[16][4];
    u32 AF[16][4], XF[6][4];
    const float bd0 = __ldg(bd);
    const long long NPTS = (long long)ntiles * 128;

    // per-thread B offsets: n_local * rowbytes + quad v4 offset
    const u32 t192 = (u32)(nl * 192 + q * 16);
    const u32 t576 = (u32)(nl * 576 + q * 16);
    const u32 t704 = (u32)(nl * 704 + q * 16);

    for (int tile = blockIdx.x; tile < ntiles; tile += gridDim.x) {
        // ---- xyz harmonic embed into smem: 2 threads per point ----
        {
            int p = tid & 127, half = tid >> 7;
            const float* qp = pts + ((long long)tile * 128 + p) * 3;
            float v0 = __ldg(qp), v1 = __ldg(qp + 1), v2 = __ldg(qp + 2);
            float* er = esm + p * ESTRIDE;
            if (half == 0) {
                float fr = 1.f;
#pragma unroll
                for (int f = 0; f < 6; f++) {
                    float s, c; sincosf(v0 * fr, &s, &c);
                    er[f] = s; er[18 + f] = c; fr *= 2.f;
                }
                fr = 1.f;
#pragma unroll
                for (int f = 0; f < 3; f++) {
                    float s, c; sincosf(v2 * fr, &s, &c);
                    er[12 + f] = s; er[30 + f] = c; fr *= 2.f;
                }
                er[36] = v0; er[37] = v1; er[38] = v2;
#pragma unroll
                for (int i = 39; i < 48; i++) er[i] = 0.f;
            } else {
                float fr = 1.f;
#pragma unroll
                for (int f = 0; f < 6; f++) {
                    float s, c; sincosf(v1 * fr, &s, &c);
                    er[6 + f] = s; er[24 + f] = c; fr *= 2.f;
                }
                fr = 8.f;
#pragma unroll
                for (int f = 3; f < 6; f++) {
                    float s, c; sincosf(v2 * fr, &s, &c);
                    er[12 + f] = s; er[30 + f] = c; fr *= 2.f;
                }
            }
        }
        __syncthreads();

        // ---- xyz X-frags (natural slot order; kept until L3) ----
#pragma unroll
        for (int f = 0; f < 6; f++) {
            const float* e0 = esm + r0 * ESTRIDE + 8 * f;
            const float* e1 = esm + (r0 + 8) * ESTRIDE + 8 * f;
            XF[f][0] = cvt_tf32(e0[q]);
            XF[f][1] = cvt_tf32(e1[q]);
            XF[f][2] = cvt_tf32(e0[q + 4]);
            XF[f][3] = cvt_tf32(e1[q + 4]);
        }

        // ---- L0 (48 slots, xyz only) ----
        copy_async(wb1, g_wimg + 24576, 73728, tid);
        gemm_layer<0, 3, 16, 192>(C, AF, XF, wb0 + t192);
        epi_std<true>(C, AF, biasS, q2);
        CPW(); __syncthreads();

        // ---- L1 ----
        copy_async(wb0, g_wimg + 98304, 73728, tid);
        gemm_layer<8, 0, 16, 576>(C, AF, XF, wb1 + t576);
        epi_std<true>(C, AF, biasS + 128, q2);
        CPW(); __syncthreads();

        // ---- L2 ----
        copy_async(wb1, g_wimg + 172032, 90112, tid);
        gemm_layer<8, 0, 16, 576>(C, AF, XF, wb0 + t576);
        epi_std<true>(C, AF, biasS + 256, q2);
        CPW(); __syncthreads();

        // ---- L3 (skip: concat(y, xyz), 176 slots) ----
        copy_async(wb0, g_wimg + 262144, 73728, tid);
        gemm_layer<8, 3, 16, 704>(C, AF, XF, wb1 + t704);
        epi_std<true>(C, AF, biasS + 384, q2);
        CPW(); __syncthreads();

        // ---- L4 ----
        copy_async(wb1, g_wimg + 335872, 73728, tid);
        gemm_layer<8, 0, 16, 576>(C, AF, XF, wb0 + t576);
        epi_std<true>(C, AF, biasS + 512, q2);
        CPW(); __syncthreads();

        // ---- L5 (+fused density head) ----
        copy_async(wb0, g_wimg + 409600, 73728, tid);
        gemm_layer<8, 0, 16, 576>(C, AF, XF, wb1 + t576);
        {
            const float* bias = biasS + 640;
            float d0 = 0.f, d1 = 0.f;
#pragma unroll
            for (int nt = 0; nt < 16; nt++) {
                float2 b = *(const float2*)(bias + 8 * nt + q2);
                float2 w = *(const float2*)(wcS + 8 * nt + q2);
                float f0 = fmaxf(C[nt][0] + b.x, 0.f), f1 = fmaxf(C[nt][1] + b.y, 0.f);
                float f2 = fmaxf(C[nt][2] + b.x, 0.f), f3 = fmaxf(C[nt][3] + b.y, 0.f);
                d0 += f0 * w.x + f1 * w.y;
                d1 += f2 * w.x + f3 * w.y;
                AF[nt][0] = cvt_tf32(f0); AF[nt][1] = cvt_tf32(f2);
                AF[nt][2] = cvt_tf32(f1); AF[nt][3] = cvt_tf32(f3);
            }
            d0 += __shfl_xor_sync(0xffffffffu, d0, 1); d0 += __shfl_xor_sync(0xffffffffu, d0, 2);
            d1 += __shfl_xor_sync(0xffffffffu, d1, 1); d1 += __shfl_xor_sync(0xffffffffu, d1, 2);
            if (q == 0) {
                long long base = (long long)tile * 128;
                out[base + r0]     = fmaxf(d0 + bd0, 0.f);
                out[base + r0 + 8] = fmaxf(d1 + bd0, 0.f);
            }
        }
        CPW(); __syncthreads();

        // ---- L6 (wd cols 1..128, NO relu) ----
        copy_async(wb1, g_wimg + 483328, 36864, tid);
        gemm_layer<8, 0, 16, 576>(C, AF, XF, wb0 + t576);
        epi_std<false>(C, AF, biasS + 768, q2);
        CPW(); __syncthreads();

        // ---- dir embed frags -> XF[0..1] (xyz frags dead after L3) ----
        {
            const float* dp = dirs + (long long)tile * 3;
            float d[16];
#pragma unroll
            for (int c = 0; c < 3; c++) {
                float v = __ldg(dp + c);
                float s0, cc0, s1, cc1;
                sincosf(v, &s0, &cc0); sincosf(2.f * v, &s1, &cc1);
                d[2*c] = s0; d[2*c+1] = s1; d[6+2*c] = cc0; d[7+2*c] = cc1; d[12+c] = v;
            }
            d[15] = 0.f;
            XF[0][0] = cvt_tf32(d[q]);      XF[0][1] = XF[0][0];
            XF[0][2] = cvt_tf32(d[4 + q]);  XF[0][3] = XF[0][2];
            XF[1][0] = cvt_tf32(d[8 + q]);  XF[1][1] = XF[1][0];
            XF[1][2] = cvt_tf32(d[12 + q]); XF[1][3] = XF[1][2];
        }

        // ---- L7 (wr1: concat(feat, dir) -> 64, +fused rgb head) ----
        copy_async(wb0, g_wimg, 24576, tid);   // next tile's L0
        gemm_layer<8, 1, 8, 576>(C, AF, XF, wb1 + t576);
        {
            const float* bias = biasS + 896;
            float p00 = 0.f, p01 = 0.f, p02 = 0.f, p10 = 0.f, p11 = 0.f, p12 = 0.f;
#pragma unroll
            for (int nt = 0; nt < 8; nt++) {
                float2 b = *(const float2*)(bias + 8 * nt + q2);
                float f0 = fmaxf(C[nt][0] + b.x, 0.f), f1 = fmaxf(C[nt][1] + b.y, 0.f);
                float f2 = fmaxf(C[nt][2] + b.x, 0.f), f3 = fmaxf(C[nt][3] + b.y, 0.f);
                int p0 = 8 * nt + q2;
                const float* wA = wr2S + p0 * 3;
                const float* wB = wr2S + (p0 + 1) * 3;
                p00 += f0 * wA[0] + f1 * wB[0];
                p01 += f0 * wA[1] + f1 * wB[1];
                p02 += f0 * wA[2] + f1 * wB[2];
                p10 += f2 * wA[0] + f3 * wB[0];
                p11 += f2 * wA[1] + f3 * wB[1];
                p12 += f2 * wA[2] + f3 * wB[2];
            }
            p00 += __shfl_xor_sync(0xffffffffu, p00, 1); p00 += __shfl_xor_sync(0xffffffffu, p00, 2);
            p01 += __shfl_xor_sync(0xffffffffu, p01, 1); p01 += __shfl_xor_sync(0xffffffffu, p01, 2);
            p02 += __shfl_xor_sync(0xffffffffu, p02, 1); p02 += __shfl_xor_sync(0xffffffffu, p02, 2);
            p10 += __shfl_xor_sync(0xffffffffu, p10, 1); p10 += __shfl_xor_sync(0xffffffffu, p10, 2);
            p11 += __shfl_xor_sync(0xffffffffu, p11, 1); p11 += __shfl_xor_sync(0xffffffffu, p11, 2);
            p12 += __shfl_xor_sync(0xffffffffu, p12, 1); p12 += __shfl_xor_sync(0xffffffffu, p12, 2);
            if (q == 0) {
                long long pb = (long long)tile * 128;
                long long o0 = NPTS + (pb + r0) * 3;
                long long o1 = NPTS + (pb + r0 + 8) * 3;
                out[o0]     = 1.f / (1.f + expf(-(p00 + br2S[0])));
                out[o0 + 1] = 1.f / (1.f + expf(-(p01 + br2S[1])));
                out[o0 + 2] = 1.f / (1.f + expf(-(p02 + br2S[2])));
                out[o1]     = 1.f / (1.f + expf(-(p10 + br2S[0])));
                out[o1 + 1] = 1.f / (1.f + expf(-(p11 + br2S[1])));
                out[o1 + 2] = 1.f / (1.f + expf(-(p12 + br2S[2])));
            }
        }
        CPW(); __syncthreads();
    }
}

extern "C" void kernel_launch(void* const* d_in, const int* in_sizes, int n_in,
                              void* d_out, int out_size)
{
    const float* pts  = (const float*)d_in[0];
    const float* dirs = (const float*)d_in[1];
    const float *w0 = (const float*)d_in[2],  *b0 = (const float*)d_in[3];
    const float *w1 = (const float*)d_in[4],  *b1 = (const float*)d_in[5];
    const float *w2 = (const float*)d_in[6],  *b2 = (const float*)d_in[7];
    const float *w3 = (const float*)d_in[8],  *b3 = (const float*)d_in[9];
    const float *w4 = (const float*)d_in[10], *b4 = (const float*)d_in[11];
    const float *w5 = (const float*)d_in[12], *b5 = (const float*)d_in[13];
    const float *wd = (const float*)d_in[14], *bd = (const float*)d_in[15];
    const float *wr1 = (const float*)d_in[16], *br1 = (const float*)d_in[17];
    const float *wr2 = (const float*)d_in[18], *br2 = (const float*)d_in[19];
    float* out = (float*)d_out;

    int ntiles = in_sizes[1] / 3;   // rays
    int nsm = 0;
    cudaDeviceGetAttribute(&nsm, cudaDevAttrMultiProcessorCount, 0);
    if (nsm <= 0) nsm = 148;
    int grid = nsm < ntiles ? nsm : ntiles;

    size_t smem = 163840 + 128 * ESTRIDE * 4 + 5392;   // ~195856
    cudaFuncSetAttribute(nerf_mma_kernel, cudaFuncAttributeMaxDynamicSharedMemorySize, (int)smem);

    prep_kernel<<<8, 512>>>(w0, w1, w2, w3, w4, w5, wd, wr1);
    nerf_mma_kernel<<<grid, NTHR, smem>>>(pts, dirs, b0, b1, b2, b3, b4, b5,
                                          bd, br1, wd, wr2, br2, out, ntiles);
}

// round 9
// speedup vs baseline: 2.2387x; 1.5215x over previous
#include <cuda_runtime.h>
#include <cuda_fp16.h>

typedef unsigned int u32; typedef unsigned short u16;
#define NTHR 256
#define ES 68   // esm row stride (floats)

// f16 weight images: transposed Wt[n][k], 32-slot quad-interleaved v4 layout.
__device__ __align__(16) unsigned char g_wimg[307200];

__device__ __forceinline__ u32 smaddr(const void* p) {
    u32 a; asm("{ .reg .u64 t; cvta.to.shared.u64 t, %1; cvt.u32.u64 %0, t; }" : "=r"(a) : "l"(p));
    return a;
}
// pack two fp32 -> f16x2 (lo in low half)
__device__ __forceinline__ u32 pkh(float lo, float hi) {
    u32 r; asm("cvt.rn.f16x2.f32 %0, %1, %2;" : "=r"(r) : "f"(hi), "f"(lo)); return r;
}
__device__ __forceinline__ void mma16816(float* c, const u32* a, u32 b0, u32 b1) {
    asm volatile("mma.sync.aligned.m16n8k16.row.col.f32.f16.f16.f32 "
                 "{%0,%1,%2,%3},{%4,%5,%6,%7},{%8,%9},{%0,%1,%2,%3};"
                 : "+f"(c[0]), "+f"(c[1]), "+f"(c[2]), "+f"(c[3])
                 : "r"(a[0]), "r"(a[1]), "r"(a[2]), "r"(a[3]), "r"(b0), "r"(b1));
}
__device__ __forceinline__ void cpa16(u32 d, const void* s) {
    asm volatile("cp.async.cg.shared.global [%0], [%1], 16;" :: "r"(d), "l"(s) : "memory");
}
#define CPC() asm volatile("cp.async.commit_group;" ::: "memory")
#define CPW() asm volatile("cp.async.wait_group 0;" ::: "memory")

__device__ __forceinline__ void copy_async(u32 dst, const unsigned char* src, int bytes, int tid) {
    for (int i = tid * 16; i < bytes; i += NTHR * 16) cpa16(dst + (u32)i, src + i);
    CPC();
}

// GEMM layer: M=128 (8 warps x 16 rows), N = NT*8, K = 32*(MPG+XPG), fp16 single-pass.
// Weight image: per n-row, 32-slot (64-byte) groups; within a group each quad q owns
// 16B = slots {2q,2q+1,2q+8,2q+9 | +16...} -> one ld.shared.v4 feeds mma kf=2g
// (V.x,V.y) and kf=2g+1 (V.z,V.w). Per (g,h): 8 LDS.128 + 16 mma, C reuse distance 8.
template <int MPG, int XPG, int NT, int STB>
__device__ __forceinline__ void gemm_layer(
    float (&C)[16][4], const u32 (&AF)[8][4], const u32 (&XF)[4][4], u32 base)
{
#pragma unroll
    for (int t = 0; t < NT; t++) { C[t][0] = 0.f; C[t][1] = 0.f; C[t][2] = 0.f; C[t][3] = 0.f; }
#pragma unroll
    for (int g = 0; g < MPG + XPG; g++) {
        u32 aA[4], aB[4];
#pragma unroll
        for (int r = 0; r < 4; r++) {
            if (g < MPG) { aA[r] = AF[2 * g][r];          aB[r] = AF[2 * g + 1][r]; }
            else         { aA[r] = XF[2 * (g - MPG)][r];  aB[r] = XF[2 * (g - MPG) + 1][r]; }
        }
        const u32 ga = base + (u32)g * 64u;   // 32 slots * 2B per k-group
#pragma unroll
        for (int h = 0; h < NT / 8; h++) {
            u32 V[8][4];
#pragma unroll
            for (int t = 0; t < 8; t++) {
                u32 ad = ga + (u32)(8 * h + t) * (8u * (u32)STB);
                asm volatile("ld.shared.v4.b32 {%0,%1,%2,%3}, [%4];"
                    : "=r"(V[t][0]), "=r"(V[t][1]), "=r"(V[t][2]), "=r"(V[t][3]) : "r"(ad));
            }
#pragma unroll
            for (int t = 0; t < 8; t++) mma16816(C[8 * h + t], aA, V[t][0], V[t][1]);
#pragma unroll
            for (int t = 0; t < 8; t++) mma16816(C[8 * h + t], aB, V[t][2], V[t][3]);
        }
    }
}

// epilogue: C + bias (+relu) -> f16x2 pack into next-layer A frags (natural order)
template <bool RELU>
__device__ __forceinline__ void epi_std(float (&C)[16][4], u32 (&AF)[8][4],
                                        const float* bias, int q2)
{
#pragma unroll
    for (int kf = 0; kf < 8; kf++) {
        float2 bA = *(const float2*)(bias + 16 * kf + q2);
        float2 bB = *(const float2*)(bias + 16 * kf + 8 + q2);
        float f0 = C[2*kf][0] + bA.x, f1 = C[2*kf][1] + bA.y;
        float f2 = C[2*kf][2] + bA.x, f3 = C[2*kf][3] + bA.y;
        float g0 = C[2*kf+1][0] + bB.x, g1 = C[2*kf+1][1] + bB.y;
        float g2 = C[2*kf+1][2] + bB.x, g3 = C[2*kf+1][3] + bB.y;
        if (RELU) {
            f0 = fmaxf(f0, 0.f); f1 = fmaxf(f1, 0.f); f2 = fmaxf(f2, 0.f); f3 = fmaxf(f3, 0.f);
            g0 = fmaxf(g0, 0.f); g1 = fmaxf(g1, 0.f); g2 = fmaxf(g2, 0.f); g3 = fmaxf(g3, 0.f);
        }
        AF[kf][0] = pkh(f0, f1); AF[kf][1] = pkh(f2, f3);
        AF[kf][2] = pkh(g0, g1); AF[kf][3] = pkh(g2, g3);
    }
}

// ---- prep: fp32 W[k][n] -> f16 Wt[n][pos], 32-slot quad-interleaved layout ----
__global__ void prep_kernel(const float* w0, const float* w1, const float* w2, const float* w3,
                            const float* w4, const float* w5, const float* wd, const float* wr1)
{
    const float* srcs[8] = {w0, w1, w2, w3, w4, w5, wd, wr1};
    const int Ksrc[8] = {39, 128, 128, 167, 128, 128, 128, 143};
    const int Kslt[8] = {64, 128, 128, 192, 128, 128, 128, 160};
    const int Nn[8]   = {128, 128, 128, 128, 128, 128, 128, 64};
    const int STw[8]  = {96, 160, 160, 224, 160, 160, 160, 160};   // row stride in f16 slots
    const int wst[8]  = {128, 128, 128, 128, 128, 128, 129, 64};
    const int cof[8]  = {0, 0, 0, 0, 0, 0, 1, 0};
    const int off[8]  = {0, 24576, 65536, 106496, 163840, 204800, 245760, 286720};
    int j = blockIdx.x;
    const float* src = srcs[j];
    int N = Nn[j], S = STw[j], KS = Kslt[j], tot = N * KS;
    u16* img = (u16*)(g_wimg + off[j]);
    for (int idx = threadIdx.x; idx < tot; idx += blockDim.x) {
        int n = idx / KS, s = idx - n * KS;
        float v = (s < Ksrc[j]) ? __ldg(src + (size_t)s * wst[j] + cof[j] + n) : 0.f;
        int u = s & 31, g32 = s >> 5;
        int q = (u & 7) >> 1;
        int pos = g32 * 32 + q * 8 + ((u >> 4) & 1) * 4 + ((u >> 3) & 1) * 2 + (u & 1);
        img[(size_t)n * S + pos] = __half_as_ushort(__float2half_rn(v));
    }
}

__global__ void __launch_bounds__(NTHR, 1) nerf_mma_kernel(
    const float* __restrict__ pts, const float* __restrict__ dirs,
    const float* __restrict__ b0, const float* __restrict__ b1,
    const float* __restrict__ b2, const float* __restrict__ b3,
    const float* __restrict__ b4, const float* __restrict__ b5,
    const float* __restrict__ bd, const float* __restrict__ br1,
    const float* __restrict__ wd, const float* __restrict__ wr2,
    const float* __restrict__ br2, float* __restrict__ out, int ntiles)
{
    extern __shared__ __align__(16) unsigned char sm[];
    unsigned char* wbuf0 = sm;                       // 40960  (L0/L2/L4/L6)
    unsigned char* wbuf1 = sm + 40960;               // 57344  (L1/L3/L5/L7)
    float* esm  = (float*)(sm + 98304);              // 128 x ES fp32 embed (slots 39..63 zero)
    float* aux  = (float*)(sm + 98304 + 128 * ES * 4);
    float* biasS = aux;                              // 8 x 128
    float* wcS   = aux + 1024;                       // wd col 0 (128)
    float* wr2S  = aux + 1152;                       // 64 x 3
    float* br2S  = aux + 1344;                       // 3
    const u32 wb0 = smaddr(wbuf0), wb1 = smaddr(wbuf1);

    const int tid = threadIdx.x, lane = tid & 31, wid = tid >> 5;
    const int q  = lane & 3;
    const int q2 = 2 * q;
    const int r0 = 16 * wid + (lane >> 2);
    const int nl = lane >> 2;

    // stage biases / head weights; zero esm once (slots >=39 must be 0)
    {
        const float* bp[8] = {b0, b1, b2, b3, b4, b5, bd + 1, br1};
#pragma unroll 1
        for (int l = 0; l < 8; l++) {
            int n = (l == 7) ? 64 : 128;
            for (int i = tid; i < n; i += NTHR) biasS[l * 128 + i] = __ldg(bp[l] + i);
        }
        for (int i = tid; i < 128; i += NTHR) wcS[i] = __ldg(wd + (size_t)i * 129);
        for (int i = tid; i < 192; i += NTHR) wr2S[i] = __ldg(wr2 + i);
        if (tid < 3) br2S[tid] = __ldg(br2 + tid);
        for (int i = tid; i < 128 * ES; i += NTHR) esm[i] = 0.f;
    }
    copy_async(wb0, g_wimg, 24576, tid);   // L0
    CPW();
    __syncthreads();

    float C[16][4];
    u32 AF[8][4], XF[4][4], XFd[4][4];
    const float bd0 = __ldg(bd);
    const long long NPTS = (long long)ntiles * 128;

    // per-thread B offsets (row stride bytes): nl*STB + q*16
    const u32 t192 = (u32)(nl * 192 + q * 16);
    const u32 t320 = (u32)(nl * 320 + q * 16);
    const u32 t448 = (u32)(nl * 448 + q * 16);

    for (int tile = blockIdx.x; tile < ntiles; tile += gridDim.x) {
        // ---- xyz harmonic embed into esm (fp32): 2 threads per point ----
        {
            int p = tid & 127, half = tid >> 7;
            const float* qp = pts + ((long long)tile * 128 + p) * 3;
            float v0 = __ldg(qp), v1 = __ldg(qp + 1), v2 = __ldg(qp + 2);
            float* er = esm + p * ES;
            if (half == 0) {
                float fr = 1.f;
#pragma unroll
                for (int f = 0; f < 6; f++) {
                    float s, c; sincosf(v0 * fr, &s, &c);
                    er[f] = s; er[18 + f] = c; fr *= 2.f;
                }
                fr = 1.f;
#pragma unroll
                for (int f = 0; f < 3; f++) {
                    float s, c; sincosf(v2 * fr, &s, &c);
                    er[12 + f] = s; er[30 + f] = c; fr *= 2.f;
                }
                er[36] = v0; er[37] = v1; er[38] = v2;
            } else {
                float fr = 1.f;
#pragma unroll
                for (int f = 0; f < 6; f++) {
                    float s, c; sincosf(v1 * fr, &s, &c);
                    er[6 + f] = s; er[24 + f] = c; fr *= 2.f;
                }
                fr = 8.f;
#pragma unroll
                for (int f = 3; f < 6; f++) {
                    float s, c; sincosf(v2 * fr, &s, &c);
                    er[12 + f] = s; er[30 + f] = c; fr *= 2.f;
                }
            }
        }
        __syncthreads();

        // ---- xyz X-frags: 4 kf (slots 0..63; >=39 are zero) ----
#pragma unroll
        for (int f = 0; f < 4; f++) {
            const float* e0 = esm + r0 * ES + 16 * f;
            const float* e1 = e0 + 8 * ES;
            float2 a = *(const float2*)(e0 + q2);
            float2 b = *(const float2*)(e1 + q2);
            float2 c = *(const float2*)(e0 + q2 + 8);
            float2 d = *(const float2*)(e1 + q2 + 8);
            XF[f][0] = pkh(a.x, a.y); XF[f][1] = pkh(b.x, b.y);
            XF[f][2] = pkh(c.x, c.y); XF[f][3] = pkh(d.x, d.y);
        }

        // ---- L0 (64 slots, xyz only) ----
        copy_async(wb1, g_wimg + 24576, 40960, tid);
        gemm_layer<0, 2, 16, 192>(C, AF, XF, wb0 + t192);
        epi_std<true>(C, AF, biasS, q2);
        CPW(); __syncthreads();

        // ---- L1 ----
        copy_async(wb0, g_wimg + 65536, 40960, tid);
        gemm_layer<4, 0, 16, 320>(C, AF, XF, wb1 + t320);
        epi_std<true>(C, AF, biasS + 128, q2);
        CPW(); __syncthreads();

        // ---- L2 ----
        copy_async(wb1, g_wimg + 106496, 57344, tid);
        gemm_layer<4, 0, 16, 320>(C, AF, XF, wb0 + t320);
        epi_std<true>(C, AF, biasS + 256, q2);
        CPW(); __syncthreads();

        // ---- L3 (skip: concat(y, xyz), 192 slots) ----
        copy_async(wb0, g_wimg + 163840, 40960, tid);
        gemm_layer<4, 2, 16, 448>(C, AF, XF, wb1 + t448);
        epi_std<true>(C, AF, biasS + 384, q2);
        CPW(); __syncthreads();

        // ---- L4 ----
        copy_async(wb1, g_wimg + 204800, 40960, tid);
        gemm_layer<4, 0, 16, 320>(C, AF, XF, wb0 + t320);
        epi_std<true>(C, AF, biasS + 512, q2);
        CPW(); __syncthreads();

        // ---- L5 (+fused density head) ----
        copy_async(wb0, g_wimg + 245760, 40960, tid);
        gemm_layer<4, 0, 16, 320>(C, AF, XF, wb1 + t320);
        {
            const float* bias = biasS + 640;
            float d0 = 0.f, d1 = 0.f;
#pragma unroll
            for (int kf = 0; kf < 8; kf++) {
                float2 bA = *(const float2*)(bias + 16 * kf + q2);
                float2 bB = *(const float2*)(bias + 16 * kf + 8 + q2);
                float2 wA = *(const float2*)(wcS + 16 * kf + q2);
                float2 wB = *(const float2*)(wcS + 16 * kf + 8 + q2);
                float f0 = fmaxf(C[2*kf][0] + bA.x, 0.f), f1 = fmaxf(C[2*kf][1] + bA.y, 0.f);
                float f2 = fmaxf(C[2*kf][2] + bA.x, 0.f), f3 = fmaxf(C[2*kf][3] + bA.y, 0.f);
                float g0 = fmaxf(C[2*kf+1][0] + bB.x, 0.f), g1 = fmaxf(C[2*kf+1][1] + bB.y, 0.f);
                float g2 = fmaxf(C[2*kf+1][2] + bB.x, 0.f), g3 = fmaxf(C[2*kf+1][3] + bB.y, 0.f);
                d0 += f0 * wA.x + f1 * wA.y + g0 * wB.x + g1 * wB.y;
                d1 += f2 * wA.x + f3 * wA.y + g2 * wB.x + g3 * wB.y;
                AF[kf][0] = pkh(f0, f1); AF[kf][1] = pkh(f2, f3);
                AF[kf][2] = pkh(g0, g1); AF[kf][3] = pkh(g2, g3);
            }
            d0 += __shfl_xor_sync(0xffffffffu, d0, 1); d0 += __shfl_xor_sync(0xffffffffu, d0, 2);
            d1 += __shfl_xor_sync(0xffffffffu, d1, 1); d1 += __shfl_xor_sync(0xffffffffu, d1, 2);
            if (q == 0) {
                long long base = (long long)tile * 128;
                out[base + r0]     = fmaxf(d0 + bd0, 0.f);
                out[base + r0 + 8] = fmaxf(d1 + bd0, 0.f);
            }
        }
        CPW(); __syncthreads();

        // ---- L6 (wd cols 1..128, NO relu) ----
        copy_async(wb1, g_wimg + 286720, 20480, tid);
        gemm_layer<4, 0, 16, 320>(C, AF, XF, wb0 + t320);
        epi_std<false>(C, AF, biasS + 768, q2);
        CPW(); __syncthreads();

        // ---- dir embed frags -> XFd[0..1] ----
        {
            const float* dp = dirs + (long long)tile * 3;
            float d[16];
#pragma unroll
            for (int c = 0; c < 3; c++) {
                float v = __ldg(dp + c);
                float s0, cc0, s1, cc1;
                sincosf(v, &s0, &cc0); sincosf(2.f * v, &s1, &cc1);
                d[2*c] = s0; d[2*c+1] = s1; d[6+2*c] = cc0; d[7+2*c] = cc1; d[12+c] = v;
            }
            d[15] = 0.f;
            XFd[0][0] = pkh(d[q2], d[q2+1]);       XFd[0][1] = XFd[0][0];
            XFd[0][2] = pkh(d[8+q2], d[9+q2]);     XFd[0][3] = XFd[0][2];
            XFd[1][0] = 0u; XFd[1][1] = 0u; XFd[1][2] = 0u; XFd[1][3] = 0u;
        }

        // ---- L7 (wr1: concat(feat, dir) -> 64, 160 slots, +fused rgb head) ----
        copy_async(wb0, g_wimg, 24576, tid);   // next tile's L0
        gemm_layer<4, 1, 8, 320>(C, AF, XFd, wb1 + t320);
        {
            const float* bias = biasS + 896;
            float p00 = 0.f, p01 = 0.f, p02 = 0.f, p10 = 0.f, p11 = 0.f, p12 = 0.f;
#pragma unroll
            for (int nt = 0; nt < 8; nt++) {
                float2 b = *(const float2*)(bias + 8 * nt + q2);
                float f0 = fmaxf(C[nt][0] + b.x, 0.f), f1 = fmaxf(C[nt][1] + b.y, 0.f);
                float f2 = fmaxf(C[nt][2] + b.x, 0.f), f3 = fmaxf(C[nt][3] + b.y, 0.f);
                int p0 = 8 * nt + q2;
                const float* wA = wr2S + p0 * 3;
                const float* wB = wr2S + (p0 + 1) * 3;
                p00 += f0 * wA[0] + f1 * wB[0];
                p01 += f0 * wA[1] + f1 * wB[1];
                p02 += f0 * wA[2] + f1 * wB[2];
                p10 += f2 * wA[0] + f3 * wB[0];
                p11 += f2 * wA[1] + f3 * wB[1];
                p12 += f2 * wA[2] + f3 * wB[2];
            }
            p00 += __shfl_xor_sync(0xffffffffu, p00, 1); p00 += __shfl_xor_sync(0xffffffffu, p00, 2);
            p01 += __shfl_xor_sync(0xffffffffu, p01, 1); p01 += __shfl_xor_sync(0xffffffffu, p01, 2);
            p02 += __shfl_xor_sync(0xffffffffu, p02, 1); p02 += __shfl_xor_sync(0xffffffffu, p02, 2);
            p10 += __shfl_xor_sync(0xffffffffu, p10, 1); p10 += __shfl_xor_sync(0xffffffffu, p10, 2);
            p11 += __shfl_xor_sync(0xffffffffu, p11, 1); p11 += __shfl_xor_sync(0xffffffffu, p11, 2);
            p12 += __shfl_xor_sync(0xffffffffu, p12, 1); p12 += __shfl_xor_sync(0xffffffffu, p12, 2);
            if (q == 0) {
                long long pb = (long long)tile * 128;
                long long o0 = NPTS + (pb + r0) * 3;
                long long o1 = NPTS + (pb + r0 + 8) * 3;
                out[o0]     = 1.f / (1.f + expf(-(p00 + br2S[0])));
                out[o0 + 1] = 1.f / (1.f + expf(-(p01 + br2S[1])));
                out[o0 + 2] = 1.f / (1.f + expf(-(p02 + br2S[2])));
                out[o1]     = 1.f / (1.f + expf(-(p10 + br2S[0])));
                out[o1 + 1] = 1.f / (1.f + expf(-(p11 + br2S[1])));
                out[o1 + 2] = 1.f / (1.f + expf(-(p12 + br2S[2])));
            }
        }
        CPW(); __syncthreads();
    }
}

extern "C" void kernel_launch(void* const* d_in, const int* in_sizes, int n_in,
                              void* d_out, int out_size)
{
    const float* pts  = (const float*)d_in[0];
    const float* dirs = (const float*)d_in[1];
    const float *w0 = (const float*)d_in[2],  *b0 = (const float*)d_in[3];
    const float *w1 = (const float*)d_in[4],  *b1 = (const float*)d_in[5];
    const float *w2 = (const float*)d_in[6],  *b2 = (const float*)d_in[7];
    const float *w3 = (const float*)d_in[8],  *b3 = (const float*)d_in[9];
    const float *w4 = (const float*)d_in[10], *b4 = (const float*)d_in[11];
    const float *w5 = (const float*)d_in[12], *b5 = (const float*)d_in[13];
    const float *wd = (const float*)d_in[14], *bd = (const float*)d_in[15];
    const float *wr1 = (const float*)d_in[16], *br1 = (const float*)d_in[17];
    const float *wr2 = (const float*)d_in[18], *br2 = (const float*)d_in[19];
    float* out = (float*)d_out;

    int ntiles = in_sizes[1] / 3;   // rays
    int nsm = 0;
    cudaDeviceGetAttribute(&nsm, cudaDevAttrMultiProcessorCount, 0);
    if (nsm <= 0) nsm = 148;
    int grid = nsm < ntiles ? nsm : ntiles;

    size_t smem = 98304 + 128 * ES * 4 + 5392;   // 138512
    cudaFuncSetAttribute(nerf_mma_kernel, cudaFuncAttributeMaxDynamicSharedMemorySize, (int)smem);

    prep_kernel<<<8, 512>>>(w0, w1, w2, w3, w4, w5, wd, wr1);
    nerf_mma_kernel<<<grid, NTHR, smem>>>(pts, dirs, b0, b1, b2, b3, b4, b5,
                                          bd, br1, wd, wr2, br2, out, ntiles);
}

// round 10
// speedup vs baseline: 2.4147x; 1.0786x over previous
#include <cuda_runtime.h>
#include <cuda_fp16.h>

typedef unsigned int u32; typedef unsigned short u16;
#define NTHR 256
#define ES 68   // esm row stride (floats)

// f16 weight images: transposed Wt[n][k], 32-slot quad-interleaved v4 layout.
__device__ __align__(16) unsigned char g_wimg[307200];

__device__ __forceinline__ u32 smaddr(const void* p) {
    u32 a; asm("{ .reg .u64 t; cvta.to.shared.u64 t, %1; cvt.u32.u64 %0, t; }" : "=r"(a) : "l"(p));
    return a;
}
__device__ __forceinline__ u32 pkh(float lo, float hi) {
    u32 r; asm("cvt.rn.f16x2.f32 %0, %1, %2;" : "=r"(r) : "f"(hi), "f"(lo)); return r;
}
__device__ __forceinline__ void mma16816(float* c, const u32* a, u32 b0, u32 b1) {
    asm volatile("mma.sync.aligned.m16n8k16.row.col.f32.f16.f16.f32 "
                 "{%0,%1,%2,%3},{%4,%5,%6,%7},{%8,%9},{%0,%1,%2,%3};"
                 : "+f"(c[0]), "+f"(c[1]), "+f"(c[2]), "+f"(c[3])
                 : "r"(a[0]), "r"(a[1]), "r"(a[2]), "r"(a[3]), "r"(b0), "r"(b1));
}
__device__ __forceinline__ void cpa16(u32 d, const void* s) {
    asm volatile("cp.async.cg.shared.global [%0], [%1], 16;" :: "r"(d), "l"(s) : "memory");
}
#define CPC() asm volatile("cp.async.commit_group;" ::: "memory")
#define CPW() asm volatile("cp.async.wait_group 0;" ::: "memory")

__device__ __forceinline__ void copy_async(u32 dst, const unsigned char* src, int bytes, int tid) {
    for (int i = tid * 16; i < bytes; i += NTHR * 16) cpa16(dst + (u32)i, src + i);
    CPC();
}

// Dual-tile GEMM layer: two independent M=128 tiles share every loaded B fragment.
// K = 32*(MPG+XPG). Per (g, h-quarter): 4 LDS.128 -> 16 mma (4 per tile-kf pair).
template <int MPG, int XPG, int NT, int STB>
__device__ __forceinline__ void gemm_dual(
    float (&C0)[16][4], float (&C1)[16][4],
    const u32 (&AF0)[8][4], const u32 (&AF1)[8][4],
    const u32 (&XF0)[4][4], const u32 (&XF1)[4][4], u32 base)
{
#pragma unroll
    for (int t = 0; t < NT; t++) {
        C0[t][0] = 0.f; C0[t][1] = 0.f; C0[t][2] = 0.f; C0[t][3] = 0.f;
        C1[t][0] = 0.f; C1[t][1] = 0.f; C1[t][2] = 0.f; C1[t][3] = 0.f;
    }
#pragma unroll
    for (int g = 0; g < MPG + XPG; g++) {
        u32 aA0[4], aB0[4], aA1[4], aB1[4];
#pragma unroll
        for (int r = 0; r < 4; r++) {
            if (g < MPG) {
                aA0[r] = AF0[2*g][r];   aB0[r] = AF0[2*g+1][r];
                aA1[r] = AF1[2*g][r];   aB1[r] = AF1[2*g+1][r];
            } else {
                aA0[r] = XF0[2*(g-MPG)][r];   aB0[r] = XF0[2*(g-MPG)+1][r];
                aA1[r] = XF1[2*(g-MPG)][r];   aB1[r] = XF1[2*(g-MPG)+1][r];
            }
        }
        const u32 ga = base + (u32)g * 64u;   // 32 slots * 2B per k-group
#pragma unroll
        for (int h = 0; h < NT / 4; h++) {
            u32 V[4][4];
#pragma unroll
            for (int t = 0; t < 4; t++) {
                u32 ad = ga + (u32)(4 * h + t) * (8u * (u32)STB);
                asm volatile("ld.shared.v4.b32 {%0,%1,%2,%3}, [%4];"
                    : "=r"(V[t][0]), "=r"(V[t][1]), "=r"(V[t][2]), "=r"(V[t][3]) : "r"(ad));
            }
#pragma unroll
            for (int t = 0; t < 4; t++) {
                mma16816(C0[4*h+t], aA0, V[t][0], V[t][1]);
                mma16816(C1[4*h+t], aA1, V[t][0], V[t][1]);
                mma16816(C0[4*h+t], aB0, V[t][2], V[t][3]);
                mma16816(C1[4*h+t], aB1, V[t][2], V[t][3]);
            }
        }
    }
}

// epilogue: C + bias (+relu) -> f16x2 pack into next-layer A frags
template <bool RELU>
__device__ __forceinline__ void epi_std(float (&C)[16][4], u32 (&AF)[8][4],
                                        const float* bias, int q2)
{
#pragma unroll
    for (int kf = 0; kf < 8; kf++) {
        float2 bA = *(const float2*)(bias + 16 * kf + q2);
        float2 bB = *(const float2*)(bias + 16 * kf + 8 + q2);
        float f0 = C[2*kf][0] + bA.x, f1 = C[2*kf][1] + bA.y;
        float f2 = C[2*kf][2] + bA.x, f3 = C[2*kf][3] + bA.y;
        float g0 = C[2*kf+1][0] + bB.x, g1 = C[2*kf+1][1] + bB.y;
        float g2 = C[2*kf+1][2] + bB.x, g3 = C[2*kf+1][3] + bB.y;
        if (RELU) {
            f0 = fmaxf(f0, 0.f); f1 = fmaxf(f1, 0.f); f2 = fmaxf(f2, 0.f); f3 = fmaxf(f3, 0.f);
            g0 = fmaxf(g0, 0.f); g1 = fmaxf(g1, 0.f); g2 = fmaxf(g2, 0.f); g3 = fmaxf(g3, 0.f);
        }
        AF[kf][0] = pkh(f0, f1); AF[kf][1] = pkh(f2, f3);
        AF[kf][2] = pkh(g0, g1); AF[kf][3] = pkh(g2, g3);
    }
}

// L5 epilogue with fused density head
__device__ __forceinline__ void epi_dens(float (&C)[16][4], u32 (&AF)[8][4],
                                         const float* bias, const float* wcS,
                                         float bd0, float* out, long long base,
                                         int q2, int q, int r0)
{
    float d0 = 0.f, d1 = 0.f;
#pragma unroll
    for (int kf = 0; kf < 8; kf++) {
        float2 bA = *(const float2*)(bias + 16 * kf + q2);
        float2 bB = *(const float2*)(bias + 16 * kf + 8 + q2);
        float2 wA = *(const float2*)(wcS + 16 * kf + q2);
        float2 wB = *(const float2*)(wcS + 16 * kf + 8 + q2);
        float f0 = fmaxf(C[2*kf][0] + bA.x, 0.f), f1 = fmaxf(C[2*kf][1] + bA.y, 0.f);
        float f2 = fmaxf(C[2*kf][2] + bA.x, 0.f), f3 = fmaxf(C[2*kf][3] + bA.y, 0.f);
        float g0 = fmaxf(C[2*kf+1][0] + bB.x, 0.f), g1 = fmaxf(C[2*kf+1][1] + bB.y, 0.f);
        float g2 = fmaxf(C[2*kf+1][2] + bB.x, 0.f), g3 = fmaxf(C[2*kf+1][3] + bB.y, 0.f);
        d0 += f0 * wA.x + f1 * wA.y + g0 * wB.x + g1 * wB.y;
        d1 += f2 * wA.x + f3 * wA.y + g2 * wB.x + g3 * wB.y;
        AF[kf][0] = pkh(f0, f1); AF[kf][1] = pkh(f2, f3);
        AF[kf][2] = pkh(g0, g1); AF[kf][3] = pkh(g2, g3);
    }
    d0 += __shfl_xor_sync(0xffffffffu, d0, 1); d0 += __shfl_xor_sync(0xffffffffu, d0, 2);
    d1 += __shfl_xor_sync(0xffffffffu, d1, 1); d1 += __shfl_xor_sync(0xffffffffu, d1, 2);
    if (q == 0) {
        out[base + r0]     = fmaxf(d0 + bd0, 0.f);
        out[base + r0 + 8] = fmaxf(d1 + bd0, 0.f);
    }
}

// L7 epilogue: relu + rgb head (wr2 + sigmoid)
__device__ __forceinline__ void epi_rgb(float (&C)[16][4], const float* bias,
                                        const float* wr2S, const float* br2S,
                                        float* out, long long obase,
                                        int q2, int q, int r0)
{
    float p00 = 0.f, p01 = 0.f, p02 = 0.f, p10 = 0.f, p11 = 0.f, p12 = 0.f;
#pragma unroll
    for (int nt = 0; nt < 8; nt++) {
        float2 b = *(const float2*)(bias + 8 * nt + q2);
        float f0 = fmaxf(C[nt][0] + b.x, 0.f), f1 = fmaxf(C[nt][1] + b.y, 0.f);
        float f2 = fmaxf(C[nt][2] + b.x, 0.f), f3 = fmaxf(C[nt][3] + b.y, 0.f);
        int p0 = 8 * nt + q2;
        const float* wA = wr2S + p0 * 3;
        const float* wB = wr2S + (p0 + 1) * 3;
        p00 += f0 * wA[0] + f1 * wB[0];
        p01 += f0 * wA[1] + f1 * wB[1];
        p02 += f0 * wA[2] + f1 * wB[2];
        p10 += f2 * wA[0] + f3 * wB[0];
        p11 += f2 * wA[1] + f3 * wB[1];
        p12 += f2 * wA[2] + f3 * wB[2];
    }
    p00 += __shfl_xor_sync(0xffffffffu, p00, 1); p00 += __shfl_xor_sync(0xffffffffu, p00, 2);
    p01 += __shfl_xor_sync(0xffffffffu, p01, 1); p01 += __shfl_xor_sync(0xffffffffu, p01, 2);
    p02 += __shfl_xor_sync(0xffffffffu, p02, 1); p02 += __shfl_xor_sync(0xffffffffu, p02, 2);
    p10 += __shfl_xor_sync(0xffffffffu, p10, 1); p10 += __shfl_xor_sync(0xffffffffu, p10, 2);
    p11 += __shfl_xor_sync(0xffffffffu, p11, 1); p11 += __shfl_xor_sync(0xffffffffu, p11, 2);
    p12 += __shfl_xor_sync(0xffffffffu, p12, 1); p12 += __shfl_xor_sync(0xffffffffu, p12, 2);
    if (q == 0) {
        long long o0 = obase + (long long)r0 * 3;
        long long o1 = obase + (long long)(r0 + 8) * 3;
        out[o0]     = 1.f / (1.f + expf(-(p00 + br2S[0])));
        out[o0 + 1] = 1.f / (1.f + expf(-(p01 + br2S[1])));
        out[o0 + 2] = 1.f / (1.f + expf(-(p02 + br2S[2])));
        out[o1]     = 1.f / (1.f + expf(-(p10 + br2S[0])));
        out[o1 + 1] = 1.f / (1.f + expf(-(p11 + br2S[1])));
        out[o1 + 2] = 1.f / (1.f + expf(-(p12 + br2S[2])));
    }
}

// ---- prep: fp32 W[k][n] -> f16 Wt[n][pos], 32-slot quad-interleaved layout ----
__global__ void prep_kernel(const float* w0, const float* w1, const float* w2, const float* w3,
                            const float* w4, const float* w5, const float* wd, const float* wr1)
{
    const float* srcs[8] = {w0, w1, w2, w3, w4, w5, wd, wr1};
    const int Ksrc[8] = {39, 128, 128, 167, 128, 128, 128, 143};
    const int Kslt[8] = {64, 128, 128, 192, 128, 128, 128, 160};
    const int Nn[8]   = {128, 128, 128, 128, 128, 128, 128, 64};
    const int STw[8]  = {96, 160, 160, 224, 160, 160, 160, 160};
    const int wst[8]  = {128, 128, 128, 128, 128, 128, 129, 64};
    const int cof[8]  = {0, 0, 0, 0, 0, 0, 1, 0};
    const int off[8]  = {0, 24576, 65536, 106496, 163840, 204800, 245760, 286720};
    int j = blockIdx.x;
    const float* src = srcs[j];
    int N = Nn[j], S = STw[j], KS = Kslt[j], tot = N * KS;
    u16* img = (u16*)(g_wimg + off[j]);
    for (int idx = threadIdx.x; idx < tot; idx += blockDim.x) {
        int n = idx / KS, s = idx - n * KS;
        float v = (s < Ksrc[j]) ? __ldg(src + (size_t)s * wst[j] + cof[j] + n) : 0.f;
        int u = s & 31, g32 = s >> 5;
        int q = (u & 7) >> 1;
        int pos = g32 * 32 + q * 8 + ((u >> 4) & 1) * 4 + ((u >> 3) & 1) * 2 + (u & 1);
        img[(size_t)n * S + pos] = __half_as_ushort(__float2half_rn(v));
    }
}

__global__ void __launch_bounds__(NTHR, 1) nerf_mma_kernel(
    const float* __restrict__ pts, const float* __restrict__ dirs,
    const float* __restrict__ b0, const float* __restrict__ b1,
    const float* __restrict__ b2, const float* __restrict__ b3,
    const float* __restrict__ b4, const float* __restrict__ b5,
    const float* __restrict__ bd, const float* __restrict__ br1,
    const float* __restrict__ wd, const float* __restrict__ wr2,
    const float* __restrict__ br2, float* __restrict__ out, int ntiles)
{
    extern __shared__ __align__(16) unsigned char sm[];
    unsigned char* wbuf0 = sm;                       // 40960
    unsigned char* wbuf1 = sm + 40960;               // 57344
    float* esm  = (float*)(sm + 98304);              // 256 x ES fp32 embed (2 tiles)
    float* aux  = (float*)(sm + 98304 + 256 * ES * 4);
    float* biasS = aux;                              // 8 x 128
    float* wcS   = aux + 1024;                       // wd col 0
    float* wr2S  = aux + 1152;                       // 64 x 3
    float* br2S  = aux + 1344;                       // 3
    const u32 wb0 = smaddr(wbuf0), wb1 = smaddr(wbuf1);

    const int tid = threadIdx.x, lane = tid & 31, wid = tid >> 5;
    const int q  = lane & 3;
    const int q2 = 2 * q;
    const int r0 = 16 * wid + (lane >> 2);
    const int nl = lane >> 2;

    {
        const float* bp[8] = {b0, b1, b2, b3, b4, b5, bd + 1, br1};
#pragma unroll 1
        for (int l = 0; l < 8; l++) {
            int n = (l == 7) ? 64 : 128;
            for (int i = tid; i < n; i += NTHR) biasS[l * 128 + i] = __ldg(bp[l] + i);
        }
        for (int i = tid; i < 128; i += NTHR) wcS[i] = __ldg(wd + (size_t)i * 129);
        for (int i = tid; i < 192; i += NTHR) wr2S[i] = __ldg(wr2 + i);
        if (tid < 3) br2S[tid] = __ldg(br2 + tid);
        for (int i = tid; i < 256 * ES; i += NTHR) esm[i] = 0.f;
    }
    copy_async(wb0, g_wimg, 24576, tid);   // L0
    CPW();
    __syncthreads();

    float C0[16][4], C1[16][4];
    u32 AF0[8][4], AF1[8][4], XF0[4][4], XF1[4][4];
    const float bd0 = __ldg(bd);
    const long long NPTS = (long long)ntiles * 128;
    const int npairs = ntiles >> 1;

    const u32 t192 = (u32)(nl * 192 + q * 16);
    const u32 t320 = (u32)(nl * 320 + q * 16);
    const u32 t448 = (u32)(nl * 448 + q * 16);

    for (int pair = blockIdx.x; pair < npairs; pair += gridDim.x) {
        // ---- xyz harmonic embed for BOTH tiles (2 threads per point, 2 passes) ----
#pragma unroll 1
        for (int p2 = 0; p2 < 2; p2++) {
            int p = tid & 127, half = tid >> 7;
            const float* qp = pts + (((long long)(2 * pair + p2)) * 128 + p) * 3;
            float v0 = __ldg(qp), v1 = __ldg(qp + 1), v2 = __ldg(qp + 2);
            float* er = esm + (p2 * 128 + p) * ES;
            if (half == 0) {
                float fr = 1.f;
#pragma unroll
                for (int f = 0; f < 6; f++) {
                    float s, c; sincosf(v0 * fr, &s, &c);
                    er[f] = s; er[18 + f] = c; fr *= 2.f;
                }
                fr = 1.f;
#pragma unroll
                for (int f = 0; f < 3; f++) {
                    float s, c; sincosf(v2 * fr, &s, &c);
                    er[12 + f] = s; er[30 + f] = c; fr *= 2.f;
                }
                er[36] = v0; er[37] = v1; er[38] = v2;
            } else {
                float fr = 1.f;
#pragma unroll
                for (int f = 0; f < 6; f++) {
                    float s, c; sincosf(v1 * fr, &s, &c);
                    er[6 + f] = s; er[24 + f] = c; fr *= 2.f;
                }
                fr = 8.f;
#pragma unroll
                for (int f = 3; f < 6; f++) {
                    float s, c; sincosf(v2 * fr, &s, &c);
                    er[12 + f] = s; er[30 + f] = c; fr *= 2.f;
                }
            }
        }
        __syncthreads();

        // ---- xyz X-frags for both tiles ----
#pragma unroll
        for (int f = 0; f < 4; f++) {
            const float* e0 = esm + r0 * ES + 16 * f;
            const float* e1 = e0 + 8 * ES;
            float2 a = *(const float2*)(e0 + q2);
            float2 b = *(const float2*)(e1 + q2);
            float2 c = *(const float2*)(e0 + q2 + 8);
            float2 d = *(const float2*)(e1 + q2 + 8);
            XF0[f][0] = pkh(a.x, a.y); XF0[f][1] = pkh(b.x, b.y);
            XF0[f][2] = pkh(c.x, c.y); XF0[f][3] = pkh(d.x, d.y);
            const float* f0p = esm + (128 + r0) * ES + 16 * f;
            const float* f1p = f0p + 8 * ES;
            float2 e = *(const float2*)(f0p + q2);
            float2 g = *(const float2*)(f1p + q2);
            float2 hh = *(const float2*)(f0p + q2 + 8);
            float2 k = *(const float2*)(f1p + q2 + 8);
            XF1[f][0] = pkh(e.x, e.y); XF1[f][1] = pkh(g.x, g.y);
            XF1[f][2] = pkh(hh.x, hh.y); XF1[f][3] = pkh(k.x, k.y);
        }

        // ---- L0 ----
        copy_async(wb1, g_wimg + 24576, 40960, tid);
        gemm_dual<0, 2, 16, 192>(C0, C1, AF0, AF1, XF0, XF1, wb0 + t192);
        epi_std<true>(C0, AF0, biasS, q2);
        epi_std<true>(C1, AF1, biasS, q2);
        CPW(); __syncthreads();

        // ---- L1 ----
        copy_async(wb0, g_wimg + 65536, 40960, tid);
        gemm_dual<4, 0, 16, 320>(C0, C1, AF0, AF1, XF0, XF1, wb1 + t320);
        epi_std<true>(C0, AF0, biasS + 128, q2);
        epi_std<true>(C1, AF1, biasS + 128, q2);
        CPW(); __syncthreads();

        // ---- L2 ----
        copy_async(wb1, g_wimg + 106496, 57344, tid);
        gemm_dual<4, 0, 16, 320>(C0, C1, AF0, AF1, XF0, XF1, wb0 + t320);
        epi_std<true>(C0, AF0, biasS + 256, q2);
        epi_std<true>(C1, AF1, biasS + 256, q2);
        CPW(); __syncthreads();

        // ---- L3 (skip concat, 192 slots) ----
        copy_async(wb0, g_wimg + 163840, 40960, tid);
        gemm_dual<4, 2, 16, 448>(C0, C1, AF0, AF1, XF0, XF1, wb1 + t448);
        epi_std<true>(C0, AF0, biasS + 384, q2);
        epi_std<true>(C1, AF1, biasS + 384, q2);
        CPW(); __syncthreads();

        // ---- L4 ----
        copy_async(wb1, g_wimg + 204800, 40960, tid);
        gemm_dual<4, 0, 16, 320>(C0, C1, AF0, AF1, XF0, XF1, wb0 + t320);
        epi_std<true>(C0, AF0, biasS + 512, q2);
        epi_std<true>(C1, AF1, biasS + 512, q2);
        CPW(); __syncthreads();

        // ---- L5 (+fused density heads) ----
        copy_async(wb0, g_wimg + 245760, 40960, tid);
        gemm_dual<4, 0, 16, 320>(C0, C1, AF0, AF1, XF0, XF1, wb1 + t320);
        {
            long long base0 = (long long)(2 * pair) * 128;
            epi_dens(C0, AF0, biasS + 640, wcS, bd0, out, base0,       q2, q, r0);
            epi_dens(C1, AF1, biasS + 640, wcS, bd0, out, base0 + 128, q2, q, r0);
        }
        CPW(); __syncthreads();

        // ---- L6 (wd cols 1..128, NO relu) ----
        copy_async(wb1, g_wimg + 286720, 20480, tid);
        gemm_dual<4, 0, 16, 320>(C0, C1, AF0, AF1, XF0, XF1, wb0 + t320);
        epi_std<false>(C0, AF0, biasS + 768, q2);
        epi_std<false>(C1, AF1, biasS + 768, q2);
        CPW(); __syncthreads();

        // ---- dir embeds for both tiles -> XF0/XF1[0..1] ----
#pragma unroll 1
        for (int p2 = 0; p2 < 2; p2++) {
            const float* dp = dirs + (long long)(2 * pair + p2) * 3;
            float d[16];
#pragma unroll
            for (int c = 0; c < 3; c++) {
                float v = __ldg(dp + c);
                float s0, cc0, s1, cc1;
                sincosf(v, &s0, &cc0); sincosf(2.f * v, &s1, &cc1);
                d[2*c] = s0; d[2*c+1] = s1; d[6+2*c] = cc0; d[7+2*c] = cc1; d[12+c] = v;
            }
            d[15] = 0.f;
            u32 lo = pkh(d[q2], d[q2+1]);
            u32 hi = pkh(d[8+q2], d[9+q2]);
            if (p2 == 0) {
                XF0[0][0] = lo; XF0[0][1] = lo; XF0[0][2] = hi; XF0[0][3] = hi;
                XF0[1][0] = 0u; XF0[1][1] = 0u; XF0[1][2] = 0u; XF0[1][3] = 0u;
            } else {
                XF1[0][0] = lo; XF1[0][1] = lo; XF1[0][2] = hi; XF1[0][3] = hi;
                XF1[1][0] = 0u; XF1[1][1] = 0u; XF1[1][2] = 0u; XF1[1][3] = 0u;
            }
        }

        // ---- L7 (wr1 -> 64, +fused rgb heads) ----
        copy_async(wb0, g_wimg, 24576, tid);   // next pair's L0
        gemm_dual<4, 1, 8, 320>(C0, C1, AF0, AF1, XF0, XF1, wb1 + t320);
        {
            long long pb0 = (long long)(2 * pair) * 128;
            epi_rgb(C0, biasS + 896, wr2S, br2S, out, NPTS + pb0 * 3,         q2, q, r0);
            epi_rgb(C1, biasS + 896, wr2S, br2S, out, NPTS + (pb0 + 128) * 3, q2, q, r0);
        }
        CPW(); __syncthreads();
    }
}

extern "C" void kernel_launch(void* const* d_in, const int* in_sizes, int n_in,
                              void* d_out, int out_size)
{
    const float* pts  = (const float*)d_in[0];
    const float* dirs = (const float*)d_in[1];
    const float *w0 = (const float*)d_in[2],  *b0 = (const float*)d_in[3];
    const float *w1 = (const float*)d_in[4],  *b1 = (const float*)d_in[5];
    const float *w2 = (const float*)d_in[6],  *b2 = (const float*)d_in[7];
    const float *w3 = (const float*)d_in[8],  *b3 = (const float*)d_in[9];
    const float *w4 = (const float*)d_in[10], *b4 = (const float*)d_in[11];
    const float *w5 = (const float*)d_in[12], *b5 = (const float*)d_in[13];
    const float *wd = (const float*)d_in[14], *bd = (const float*)d_in[15];
    const float *wr1 = (const float*)d_in[16], *br1 = (const float*)d_in[17];
    const float *wr2 = (const float*)d_in[18], *br2 = (const float*)d_in[19];
    float* out = (float*)d_out;

    int ntiles = in_sizes[1] / 3;   // rays
    int npairs = ntiles >> 1;
    int nsm = 0;
    cudaDeviceGetAttribute(&nsm, cudaDevAttrMultiProcessorCount, 0);
    if (nsm <= 0) nsm = 148;
    int grid = nsm < npairs ? nsm : npairs;

    size_t smem = 98304 + 256 * ES * 4 + 5392;   // ~173 KB
    cudaFuncSetAttribute(nerf_mma_kernel, cudaFuncAttributeMaxDynamicSharedMemorySize, (int)smem);

    prep_kernel<<<8, 512>>>(w0, w1, w2, w3, w4, w5, wd, wr1);
    nerf_mma_kernel<<<grid, NTHR, smem>>>(pts, dirs, b0, b1, b2, b3, b4, b5,
                                          bd, br1, wd, wr2, br2, out, ntiles);
}

// round 11
// speedup vs baseline: 2.5169x; 1.0423x over previous
#include <cuda_runtime.h>
#include <cuda_fp16.h>

typedef unsigned int u32; typedef unsigned short u16;
#define NTHR 256
#define ES 68   // esm row stride (floats)

// f16 weight images: transposed Wt[n][k], 32-slot quad-interleaved v4 layout.
__device__ __align__(16) unsigned char g_wimg[307200];

__device__ __forceinline__ u32 smaddr(const void* p) {
    u32 a; asm("{ .reg .u64 t; cvta.to.shared.u64 t, %1; cvt.u32.u64 %0, t; }" : "=r"(a) : "l"(p));
    return a;
}
__device__ __forceinline__ u32 pkh(float lo, float hi) {
    u32 r; asm("cvt.rn.f16x2.f32 %0, %1, %2;" : "=r"(r) : "f"(hi), "f"(lo)); return r;
}
__device__ __forceinline__ void mma16816(float* c, const u32* a, u32 b0, u32 b1) {
    asm volatile("mma.sync.aligned.m16n8k16.row.col.f32.f16.f16.f32 "
                 "{%0,%1,%2,%3},{%4,%5,%6,%7},{%8,%9},{%0,%1,%2,%3};"
                 : "+f"(c[0]), "+f"(c[1]), "+f"(c[2]), "+f"(c[3])
                 : "r"(a[0]), "r"(a[1]), "r"(a[2]), "r"(a[3]), "r"(b0), "r"(b1));
}
__device__ __forceinline__ void lds128(u32* v, u32 ad) {
    asm volatile("ld.shared.v4.b32 {%0,%1,%2,%3}, [%4];"
        : "=r"(v[0]), "=r"(v[1]), "=r"(v[2]), "=r"(v[3]) : "r"(ad));
}
__device__ __forceinline__ void cpa16(u32 d, const void* s) {
    asm volatile("cp.async.cg.shared.global [%0], [%1], 16;" :: "r"(d), "l"(s) : "memory");
}
#define CPC() asm volatile("cp.async.commit_group;" ::: "memory")
#define CPW() asm volatile("cp.async.wait_group 0;" ::: "memory")

__device__ __forceinline__ void copy_async(u32 dst, const unsigned char* src, int bytes, int tid) {
    for (int i = tid * 16; i < bytes; i += NTHR * 16) cpa16(dst + (u32)i, src + i);
    CPC();
}

// Build an A fragment for kf at esm column base cb (fp32 smem -> f16x2 regs).
__device__ __forceinline__ void efrag(const float* er0, int cb, int q2, u32* f) {
    float2 a = *(const float2*)(er0 + cb + q2);
    float2 b = *(const float2*)(er0 + 8 * ES + cb + q2);
    float2 c = *(const float2*)(er0 + cb + q2 + 8);
    float2 d = *(const float2*)(er0 + 8 * ES + cb + q2 + 8);
    f[0] = pkh(a.x, a.y); f[1] = pkh(b.x, b.y);
    f[2] = pkh(c.x, c.y); f[3] = pkh(d.x, d.y);
}

// Dual-tile GEMM: two M=128 tiles share every loaded B fragment.
// XMODE: 0 = AF groups only (V double-buffered); 1 = +2 esm groups (last group's
// second kf is zero-padded -> skipped); 2 = +1 dir group (aA only).
template <int MPG, int XMODE, int NT, int STB>
__device__ __forceinline__ void gemm_dual(
    float (&C0)[16][4], float (&C1)[16][4],
    const u32 (&AF0)[8][4], const u32 (&AF1)[8][4],
    u32 base, const float* e00, const float* e10,
    const u32* xd0, const u32* xd1, int q2)
{
    constexpr int NG = MPG + (XMODE == 1 ? 2 : (XMODE == 2 ? 1 : 0));
    constexpr int H = NT / 4;
#pragma unroll
    for (int t = 0; t < NT; t++) {
        C0[t][0] = 0.f; C0[t][1] = 0.f; C0[t][2] = 0.f; C0[t][3] = 0.f;
        C1[t][0] = 0.f; C1[t][1] = 0.f; C1[t][2] = 0.f; C1[t][3] = 0.f;
    }
#pragma unroll
    for (int g = 0; g < NG; g++) {
        u32 aA0[4], aB0[4], aA1[4], aB1[4];
        const bool haveB = (g < MPG) || (XMODE == 1 && g == MPG);
        if (g < MPG) {
#pragma unroll
            for (int r = 0; r < 4; r++) {
                aA0[r] = AF0[2*g][r];   aB0[r] = AF0[2*g+1][r];
                aA1[r] = AF1[2*g][r];   aB1[r] = AF1[2*g+1][r];
            }
        } else if (XMODE == 1) {
            int cb = 32 * (g - MPG);
            efrag(e00, cb, q2, aA0);
            efrag(e10, cb, q2, aA1);
            if (haveB) { efrag(e00, cb + 16, q2, aB0); efrag(e10, cb + 16, q2, aB1); }
        } else {   // XMODE == 2: dir group, aA only
#pragma unroll
            for (int r = 0; r < 4; r++) { aA0[r] = xd0[r]; aA1[r] = xd1[r]; }
        }
        const u32 ga = base + (u32)g * 64u;

        if (XMODE == 0) {
            // V double-buffer: load batch h+1 while mma'ing batch h
            u32 V[2][4][4];
#pragma unroll
            for (int t = 0; t < 4; t++) lds128(V[0][t], ga + (u32)t * (8u * (u32)STB));
#pragma unroll
            for (int h = 0; h < H; h++) {
                if (h + 1 < H) {
#pragma unroll
                    for (int t = 0; t < 4; t++)
                        lds128(V[(h+1)&1][t], ga + (u32)(4*(h+1)+t) * (8u * (u32)STB));
                }
#pragma unroll
                for (int t = 0; t < 4; t++) {
                    const u32* v = V[h&1][t];
                    mma16816(C0[4*h+t], aA0, v[0], v[1]);
                    mma16816(C1[4*h+t], aA1, v[0], v[1]);
                    mma16816(C0[4*h+t], aB0, v[2], v[3]);
                    mma16816(C1[4*h+t], aB1, v[2], v[3]);
                }
            }
        } else {
#pragma unroll
            for (int h = 0; h < H; h++) {
                u32 V[4][4];
#pragma unroll
                for (int t = 0; t < 4; t++)
                    lds128(V[t], ga + (u32)(4*h+t) * (8u * (u32)STB));
#pragma unroll
                for (int t = 0; t < 4; t++) {
                    mma16816(C0[4*h+t], aA0, V[t][0], V[t][1]);
                    mma16816(C1[4*h+t], aA1, V[t][0], V[t][1]);
                    if (haveB) {
                        mma16816(C0[4*h+t], aB0, V[t][2], V[t][3]);
                        mma16816(C1[4*h+t], aB1, V[t][2], V[t][3]);
                    }
                }
            }
        }
    }
}

// epilogue: C + bias (+relu) -> f16x2 pack into next-layer A frags
template <bool RELU>
__device__ __forceinline__ void epi_std(float (&C)[16][4], u32 (&AF)[8][4],
                                        const float* bias, int q2)
{
#pragma unroll
    for (int kf = 0; kf < 8; kf++) {
        float2 bA = *(const float2*)(bias + 16 * kf + q2);
        float2 bB = *(const float2*)(bias + 16 * kf + 8 + q2);
        float f0 = C[2*kf][0] + bA.x, f1 = C[2*kf][1] + bA.y;
        float f2 = C[2*kf][2] + bA.x, f3 = C[2*kf][3] + bA.y;
        float g0 = C[2*kf+1][0] + bB.x, g1 = C[2*kf+1][1] + bB.y;
        float g2 = C[2*kf+1][2] + bB.x, g3 = C[2*kf+1][3] + bB.y;
        if (RELU) {
            f0 = fmaxf(f0, 0.f); f1 = fmaxf(f1, 0.f); f2 = fmaxf(f2, 0.f); f3 = fmaxf(f3, 0.f);
            g0 = fmaxf(g0, 0.f); g1 = fmaxf(g1, 0.f); g2 = fmaxf(g2, 0.f); g3 = fmaxf(g3, 0.f);
        }
        AF[kf][0] = pkh(f0, f1); AF[kf][1] = pkh(f2, f3);
        AF[kf][2] = pkh(g0, g1); AF[kf][3] = pkh(g2, g3);
    }
}

// L5 epilogue with fused density head
__device__ __forceinline__ void epi_dens(float (&C)[16][4], u32 (&AF)[8][4],
                                         const float* bias, const float* wcS,
                                         float bd0, float* out, long long base,
                                         int q2, int q, int r0)
{
    float d0 = 0.f, d1 = 0.f;
#pragma unroll
    for (int kf = 0; kf < 8; kf++) {
        float2 bA = *(const float2*)(bias + 16 * kf + q2);
        float2 bB = *(const float2*)(bias + 16 * kf + 8 + q2);
        float2 wA = *(const float2*)(wcS + 16 * kf + q2);
        float2 wB = *(const float2*)(wcS + 16 * kf + 8 + q2);
        float f0 = fmaxf(C[2*kf][0] + bA.x, 0.f), f1 = fmaxf(C[2*kf][1] + bA.y, 0.f);
        float f2 = fmaxf(C[2*kf][2] + bA.x, 0.f), f3 = fmaxf(C[2*kf][3] + bA.y, 0.f);
        float g0 = fmaxf(C[2*kf+1][0] + bB.x, 0.f), g1 = fmaxf(C[2*kf+1][1] + bB.y, 0.f);
        float g2 = fmaxf(C[2*kf+1][2] + bB.x, 0.f), g3 = fmaxf(C[2*kf+1][3] + bB.y, 0.f);
        d0 += f0 * wA.x + f1 * wA.y + g0 * wB.x + g1 * wB.y;
        d1 += f2 * wA.x + f3 * wA.y + g2 * wB.x + g3 * wB.y;
        AF[kf][0] = pkh(f0, f1); AF[kf][1] = pkh(f2, f3);
        AF[kf][2] = pkh(g0, g1); AF[kf][3] = pkh(g2, g3);
    }
    d0 += __shfl_xor_sync(0xffffffffu, d0, 1); d0 += __shfl_xor_sync(0xffffffffu, d0, 2);
    d1 += __shfl_xor_sync(0xffffffffu, d1, 1); d1 += __shfl_xor_sync(0xffffffffu, d1, 2);
    if (q == 0) {
        out[base + r0]     = fmaxf(d0 + bd0, 0.f);
        out[base + r0 + 8] = fmaxf(d1 + bd0, 0.f);
    }
}

// L7 epilogue: relu + rgb head (wr2 + sigmoid)
__device__ __forceinline__ void epi_rgb(float (&C)[16][4], const float* bias,
                                        const float* wr2S, const float* br2S,
                                        float* out, long long obase,
                                        int q2, int q, int r0)
{
    float p00 = 0.f, p01 = 0.f, p02 = 0.f, p10 = 0.f, p11 = 0.f, p12 = 0.f;
#pragma unroll
    for (int nt = 0; nt < 8; nt++) {
        float2 b = *(const float2*)(bias + 8 * nt + q2);
        float f0 = fmaxf(C[nt][0] + b.x, 0.f), f1 = fmaxf(C[nt][1] + b.y, 0.f);
        float f2 = fmaxf(C[nt][2] + b.x, 0.f), f3 = fmaxf(C[nt][3] + b.y, 0.f);
        int p0 = 8 * nt + q2;
        const float* wA = wr2S + p0 * 3;
        const float* wB = wr2S + (p0 + 1) * 3;
        p00 += f0 * wA[0] + f1 * wB[0];
        p01 += f0 * wA[1] + f1 * wB[1];
        p02 += f0 * wA[2] + f1 * wB[2];
        p10 += f2 * wA[0] + f3 * wB[0];
        p11 += f2 * wA[1] + f3 * wB[1];
        p12 += f2 * wA[2] + f3 * wB[2];
    }
    p00 += __shfl_xor_sync(0xffffffffu, p00, 1); p00 += __shfl_xor_sync(0xffffffffu, p00, 2);
    p01 += __shfl_xor_sync(0xffffffffu, p01, 1); p01 += __shfl_xor_sync(0xffffffffu, p01, 2);
    p02 += __shfl_xor_sync(0xffffffffu, p02, 1); p02 += __shfl_xor_sync(0xffffffffu, p02, 2);
    p10 += __shfl_xor_sync(0xffffffffu, p10, 1); p10 += __shfl_xor_sync(0xffffffffu, p10, 2);
    p11 += __shfl_xor_sync(0xffffffffu, p11, 1); p11 += __shfl_xor_sync(0xffffffffu, p11, 2);
    p12 += __shfl_xor_sync(0xffffffffu, p12, 1); p12 += __shfl_xor_sync(0xffffffffu, p12, 2);
    if (q == 0) {
        long long o0 = obase + (long long)r0 * 3;
        long long o1 = obase + (long long)(r0 + 8) * 3;
        out[o0]     = 1.f / (1.f + expf(-(p00 + br2S[0])));
        out[o0 + 1] = 1.f / (1.f + expf(-(p01 + br2S[1])));
        out[o0 + 2] = 1.f / (1.f + expf(-(p02 + br2S[2])));
        out[o1]     = 1.f / (1.f + expf(-(p10 + br2S[0])));
        out[o1 + 1] = 1.f / (1.f + expf(-(p11 + br2S[1])));
        out[o1 + 2] = 1.f / (1.f + expf(-(p12 + br2S[2])));
    }
}

// ---- prep: fp32 W[k][n] -> f16 Wt[n][pos], 32-slot quad-interleaved layout ----
__global__ void prep_kernel(const float* w0, const float* w1, const float* w2, const float* w3,
                            const float* w4, const float* w5, const float* wd, const float* wr1)
{
    const float* srcs[8] = {w0, w1, w2, w3, w4, w5, wd, wr1};
    const int Ksrc[8] = {39, 128, 128, 167, 128, 128, 128, 143};
    const int Kslt[8] = {64, 128, 128, 192, 128, 128, 128, 160};
    const int Nn[8]   = {128, 128, 128, 128, 128, 128, 128, 64};
    const int STw[8]  = {96, 160, 160, 224, 160, 160, 160, 160};
    const int wst[8]  = {128, 128, 128, 128, 128, 128, 129, 64};
    const int cof[8]  = {0, 0, 0, 0, 0, 0, 1, 0};
    const int off[8]  = {0, 24576, 65536, 106496, 163840, 204800, 245760, 286720};
    int j = blockIdx.x;
    const float* src = srcs[j];
    int N = Nn[j], S = STw[j], KS = Kslt[j], tot = N * KS;
    u16* img = (u16*)(g_wimg + off[j]);
    for (int idx = threadIdx.x; idx < tot; idx += blockDim.x) {
        int n = idx / KS, s = idx - n * KS;
        float v = (s < Ksrc[j]) ? __ldg(src + (size_t)s * wst[j] + cof[j] + n) : 0.f;
        int u = s & 31, g32 = s >> 5;
        int q = (u & 7) >> 1;
        int pos = g32 * 32 + q * 8 + ((u >> 4) & 1) * 4 + ((u >> 3) & 1) * 2 + (u & 1);
        img[(size_t)n * S + pos] = __half_as_ushort(__float2half_rn(v));
    }
}

__global__ void __launch_bounds__(NTHR, 1) nerf_mma_kernel(
    const float* __restrict__ pts, const float* __restrict__ dirs,
    const float* __restrict__ b0, const float* __restrict__ b1,
    const float* __restrict__ b2, const float* __restrict__ b3,
    const float* __restrict__ b4, const float* __restrict__ b5,
    const float* __restrict__ bd, const float* __restrict__ br1,
    const float* __restrict__ wd, const float* __restrict__ wr2,
    const float* __restrict__ br2, float* __restrict__ out, int ntiles)
{
    extern __shared__ __align__(16) unsigned char sm[];
    unsigned char* wbuf0 = sm;                       // 40960
    unsigned char* wbuf1 = sm + 40960;               // 57344
    float* esm  = (float*)(sm + 98304);              // 256 x ES fp32 embed (2 tiles)
    float* aux  = (float*)(sm + 98304 + 256 * ES * 4);
    float* biasS = aux;                              // 8 x 128
    float* wcS   = aux + 1024;                       // wd col 0
    float* wr2S  = aux + 1152;                       // 64 x 3
    float* br2S  = aux + 1344;                       // 3
    const u32 wb0 = smaddr(wbuf0), wb1 = smaddr(wbuf1);

    const int tid = threadIdx.x, lane = tid & 31, wid = tid >> 5;
    const int q  = lane & 3;
    const int q2 = 2 * q;
    const int r0 = 16 * wid + (lane >> 2);
    const int nl = lane >> 2;

    {
        const float* bp[8] = {b0, b1, b2, b3, b4, b5, bd + 1, br1};
#pragma unroll 1
        for (int l = 0; l < 8; l++) {
            int n = (l == 7) ? 64 : 128;
            for (int i = tid; i < n; i += NTHR) biasS[l * 128 + i] = __ldg(bp[l] + i);
        }
        for (int i = tid; i < 128; i += NTHR) wcS[i] = __ldg(wd + (size_t)i * 129);
        for (int i = tid; i < 192; i += NTHR) wr2S[i] = __ldg(wr2 + i);
        if (tid < 3) br2S[tid] = __ldg(br2 + tid);
        for (int i = tid; i < 256 * ES; i += NTHR) esm[i] = 0.f;
    }
    copy_async(wb0, g_wimg, 24576, tid);   // L0
    CPW();
    __syncthreads();

    float C0[16][4], C1[16][4];
    u32 AF0[8][4], AF1[8][4];
    const float bd0 = __ldg(bd);
    const long long NPTS = (long long)ntiles * 128;
    const int npairs = ntiles >> 1;

    const u32 t192 = (u32)(nl * 192 + q * 16);
    const u32 t320 = (u32)(nl * 320 + q * 16);
    const u32 t448 = (u32)(nl * 448 + q * 16);
    const float* e00 = esm + r0 * ES;
    const float* e10 = esm + (128 + r0) * ES;

    for (int pair = blockIdx.x; pair < npairs; pair += gridDim.x) {
        // ---- xyz harmonic embed for BOTH tiles (2 threads per point, 2 passes) ----
#pragma unroll 1
        for (int p2 = 0; p2 < 2; p2++) {
            int p = tid & 127, half = tid >> 7;
            const float* qp = pts + (((long long)(2 * pair + p2)) * 128 + p) * 3;
            float v0 = __ldg(qp), v1 = __ldg(qp + 1), v2 = __ldg(qp + 2);
            float* er = esm + (p2 * 128 + p) * ES;
            if (half == 0) {
                float fr = 1.f;
#pragma unroll
                for (int f = 0; f < 6; f++) {
                    float s, c; sincosf(v0 * fr, &s, &c);
                    er[f] = s; er[18 + f] = c; fr *= 2.f;
                }
                fr = 1.f;
#pragma unroll
                for (int f = 0; f < 3; f++) {
                    float s, c; sincosf(v2 * fr, &s, &c);
                    er[12 + f] = s; er[30 + f] = c; fr *= 2.f;
                }
                er[36] = v0; er[37] = v1; er[38] = v2;
            } else {
                float fr = 1.f;
#pragma unroll
                for (int f = 0; f < 6; f++) {
                    float s, c; sincosf(v1 * fr, &s, &c);
                    er[6 + f] = s; er[24 + f] = c; fr *= 2.f;
                }
                fr = 8.f;
#pragma unroll
                for (int f = 3; f < 6; f++) {
                    float s, c; sincosf(v2 * fr, &s, &c);
                    er[12 + f] = s; er[30 + f] = c; fr *= 2.f;
                }
            }
        }
        __syncthreads();

        // ---- L0 (xyz from esm, 2 extra groups, last kf skipped) ----
        copy_async(wb1, g_wimg + 24576, 40960, tid);
        gemm_dual<0, 1, 16, 192>(C0, C1, AF0, AF1, wb0 + t192, e00, e10, 0, 0, q2);
        epi_std<true>(C0, AF0, biasS, q2);
        epi_std<true>(C1, AF1, biasS, q2);
        CPW(); __syncthreads();

        // ---- L1 ----
        copy_async(wb0, g_wimg + 65536, 40960, tid);
        gemm_dual<4, 0, 16, 320>(C0, C1, AF0, AF1, wb1 + t320, 0, 0, 0, 0, q2);
        epi_std<true>(C0, AF0, biasS + 128, q2);
        epi_std<true>(C1, AF1, biasS + 128, q2);
        CPW(); __syncthreads();

        // ---- L2 ----
        copy_async(wb1, g_wimg + 106496, 57344, tid);
        gemm_dual<4, 0, 16, 320>(C0, C1, AF0, AF1, wb0 + t320, 0, 0, 0, 0, q2);
        epi_std<true>(C0, AF0, biasS + 256, q2);
        epi_std<true>(C1, AF1, biasS + 256, q2);
        CPW(); __syncthreads();

        // ---- L3 (skip concat: 4 AF groups + 2 esm groups) ----
        copy_async(wb0, g_wimg + 163840, 40960, tid);
        gemm_dual<4, 1, 16, 448>(C0, C1, AF0, AF1, wb1 + t448, e00, e10, 0, 0, q2);
        epi_std<true>(C0, AF0, biasS + 384, q2);
        epi_std<true>(C1, AF1, biasS + 384, q2);
        CPW(); __syncthreads();

        // ---- L4 ----
        copy_async(wb1, g_wimg + 204800, 40960, tid);
        gemm_dual<4, 0, 16, 320>(C0, C1, AF0, AF1, wb0 + t320, 0, 0, 0, 0, q2);
        epi_std<true>(C0, AF0, biasS + 512, q2);
        epi_std<true>(C1, AF1, biasS + 512, q2);
        CPW(); __syncthreads();

        // ---- L5 (+fused density heads) ----
        copy_async(wb0, g_wimg + 245760, 40960, tid);
        gemm_dual<4, 0, 16, 320>(C0, C1, AF0, AF1, wb1 + t320, 0, 0, 0, 0, q2);
        {
            long long base0 = (long long)(2 * pair) * 128;
            epi_dens(C0, AF0, biasS + 640, wcS, bd0, out, base0,       q2, q, r0);
            epi_dens(C1, AF1, biasS + 640, wcS, bd0, out, base0 + 128, q2, q, r0);
        }
        CPW(); __syncthreads();

        // ---- L6 (wd cols 1..128, NO relu) ----
        copy_async(wb1, g_wimg + 286720, 20480, tid);
        gemm_dual<4, 0, 16, 320>(C0, C1, AF0, AF1, wb0 + t320, 0, 0, 0, 0, q2);
        epi_std<false>(C0, AF0, biasS + 768, q2);
        epi_std<false>(C1, AF1, biasS + 768, q2);
        CPW(); __syncthreads();

        // ---- dir frags for both tiles (4 regs each) ----
        u32 xd0[4], xd1[4];
#pragma unroll 1
        for (int p2 = 0; p2 < 2; p2++) {
            const float* dp = dirs + (long long)(2 * pair + p2) * 3;
            float d[16];
#pragma unroll
            for (int c = 0; c < 3; c++) {
                float v = __ldg(dp + c);
                float s0, cc0, s1, cc1;
                sincosf(v, &s0, &cc0); sincosf(2.f * v, &s1, &cc1);
                d[2*c] = s0; d[2*c+1] = s1; d[6+2*c] = cc0; d[7+2*c] = cc1; d[12+c] = v;
            }
            d[15] = 0.f;
            u32 lo = pkh(d[q2], d[q2+1]);
            u32 hi = pkh(d[8+q2], d[9+q2]);
            u32* xd = (p2 == 0) ? xd0 : xd1;
            xd[0] = lo; xd[1] = lo; xd[2] = hi; xd[3] = hi;
        }

        // ---- L7 (wr1 -> 64: 4 AF groups + dir group (aA only), +fused rgb heads) ----
        copy_async(wb0, g_wimg, 24576, tid);   // next pair's L0
        gemm_dual<4, 2, 8, 320>(C0, C1, AF0, AF1, wb1 + t320, 0, 0, xd0, xd1, q2);
        {
            long long pb0 = (long long)(2 * pair) * 128;
            epi_rgb(C0, biasS + 896, wr2S, br2S, out, NPTS + pb0 * 3,         q2, q, r0);
            epi_rgb(C1, biasS + 896, wr2S, br2S, out, NPTS + (pb0 + 128) * 3, q2, q, r0);
        }
        CPW(); __syncthreads();
    }
}

extern "C" void kernel_launch(void* const* d_in, const int* in_sizes, int n_in,
                              void* d_out, int out_size)
{
    const float* pts  = (const float*)d_in[0];
    const float* dirs = (const float*)d_in[1];
    const float *w0 = (const float*)d_in[2],  *b0 = (const float*)d_in[3];
    const float *w1 = (const float*)d_in[4],  *b1 = (const float*)d_in[5];
    const float *w2 = (const float*)d_in[6],  *b2 = (const float*)d_in[7];
    const float *w3 = (const float*)d_in[8],  *b3 = (const float*)d_in[9];
    const float *w4 = (const float*)d_in[10], *b4 = (const float*)d_in[11];
    const float *w5 = (const float*)d_in[12], *b5 = (const float*)d_in[13];
    const float *wd = (const float*)d_in[14], *bd = (const float*)d_in[15];
    const float *wr1 = (const float*)d_in[16], *br1 = (const float*)d_in[17];
    const float *wr2 = (const float*)d_in[18], *br2 = (const float*)d_in[19];
    float* out = (float*)d_out;

    int ntiles = in_sizes[1] / 3;   // rays
    int npairs = ntiles >> 1;
    int nsm = 0;
    cudaDeviceGetAttribute(&nsm, cudaDevAttrMultiProcessorCount, 0);
    if (nsm <= 0) nsm = 148;
    int grid = nsm < npairs ? nsm : npairs;

    size_t smem = 98304 + 256 * ES * 4 + 5392;   // ~173 KB
    cudaFuncSetAttribute(nerf_mma_kernel, cudaFuncAttributeMaxDynamicSharedMemorySize, (int)smem);

    prep_kernel<<<8, 512>>>(w0, w1, w2, w3, w4, w5, wd, wr1);
    nerf_mma_kernel<<<grid, NTHR, smem>>>(pts, dirs, b0, b1, b2, b3, b4, b5,
                                          bd, br1, wd, wr2, br2, out, ntiles);
}

// round 12
// speedup vs baseline: 2.5196x; 1.0010x over previous
#include <cuda_runtime.h>
#include <cuda_fp16.h>

typedef unsigned int u32; typedef unsigned short u16;
#define NTHR 256
#define ES 68   // esm row stride (floats)

// f16 weight images: transposed Wt[n][k], 32-slot quad-interleaved v4 layout.
__device__ __align__(16) unsigned char g_wimg[307200];

__device__ __forceinline__ u32 smaddr(const void* p) {
    u32 a; asm("{ .reg .u64 t; cvta.to.shared.u64 t, %1; cvt.u32.u64 %0, t; }" : "=r"(a) : "l"(p));
    return a;
}
__device__ __forceinline__ u32 pkh(float lo, float hi) {
    u32 r; asm("cvt.rn.f16x2.f32 %0, %1, %2;" : "=r"(r) : "f"(hi), "f"(lo)); return r;
}
__device__ __forceinline__ void mma16816(float* c, const u32* a, u32 b0, u32 b1) {
    asm volatile("mma.sync.aligned.m16n8k16.row.col.f32.f16.f16.f32 "
                 "{%0,%1,%2,%3},{%4,%5,%6,%7},{%8,%9},{%0,%1,%2,%3};"
                 : "+f"(c[0]), "+f"(c[1]), "+f"(c[2]), "+f"(c[3])
                 : "r"(a[0]), "r"(a[1]), "r"(a[2]), "r"(a[3]), "r"(b0), "r"(b1));
}
__device__ __forceinline__ void lds128(u32* v, u32 ad) {
    asm volatile("ld.shared.v4.b32 {%0,%1,%2,%3}, [%4];"
        : "=r"(v[0]), "=r"(v[1]), "=r"(v[2]), "=r"(v[3]) : "r"(ad));
}
__device__ __forceinline__ void cpa16(u32 d, const void* s) {
    asm volatile("cp.async.cg.shared.global [%0], [%1], 16;" :: "r"(d), "l"(s) : "memory");
}
#define CPC() asm volatile("cp.async.commit_group;" ::: "memory")
#define CPW() asm volatile("cp.async.wait_group 0;" ::: "memory")

__device__ __forceinline__ void copy_async(u32 dst, const unsigned char* src, int bytes, int tid) {
    for (int i = tid * 16; i < bytes; i += NTHR * 16) cpa16(dst + (u32)i, src + i);
    CPC();
}

// Build an A fragment for kf at esm column base cb (fp32 smem -> f16x2 regs).
__device__ __forceinline__ void efrag(const float* er0, int cb, int q2, u32* f) {
    float2 a = *(const float2*)(er0 + cb + q2);
    float2 b = *(const float2*)(er0 + 8 * ES + cb + q2);
    float2 c = *(const float2*)(er0 + cb + q2 + 8);
    float2 d = *(const float2*)(er0 + 8 * ES + cb + q2 + 8);
    f[0] = pkh(a.x, a.y); f[1] = pkh(b.x, b.y);
    f[2] = pkh(c.x, c.y); f[3] = pkh(d.x, d.y);
}

// Dual-tile GEMM: two M=128 tiles share every loaded B fragment.
// Inner schedule: per V-batch, ALL A-pass mmas (8) then ALL B-pass mmas (8)
// -> every accumulator's RAW reuse distance is 8 mmas (HMMA latency hidden).
// XMODE: 0 = AF groups only (V double-buffered); 1 = +2 esm groups (last group's
// second kf is zero-padded -> skipped); 2 = +1 dir group (aA only).
template <int MPG, int XMODE, int NT, int STB>
__device__ __forceinline__ void gemm_dual(
    float (&C0)[16][4], float (&C1)[16][4],
    const u32 (&AF0)[8][4], const u32 (&AF1)[8][4],
    u32 base, const float* e00, const float* e10,
    const u32* xd0, const u32* xd1, int q2)
{
    constexpr int NG = MPG + (XMODE == 1 ? 2 : (XMODE == 2 ? 1 : 0));
    constexpr int H = NT / 4;
#pragma unroll
    for (int t = 0; t < NT; t++) {
        C0[t][0] = 0.f; C0[t][1] = 0.f; C0[t][2] = 0.f; C0[t][3] = 0.f;
        C1[t][0] = 0.f; C1[t][1] = 0.f; C1[t][2] = 0.f; C1[t][3] = 0.f;
    }
#pragma unroll
    for (int g = 0; g < NG; g++) {
        u32 aA0[4], aB0[4], aA1[4], aB1[4];
        const bool haveB = (g < MPG) || (XMODE == 1 && g == MPG);
        if (g < MPG) {
#pragma unroll
            for (int r = 0; r < 4; r++) {
                aA0[r] = AF0[2*g][r];   aB0[r] = AF0[2*g+1][r];
                aA1[r] = AF1[2*g][r];   aB1[r] = AF1[2*g+1][r];
            }
        } else if (XMODE == 1) {
            int cb = 32 * (g - MPG);
            efrag(e00, cb, q2, aA0);
            efrag(e10, cb, q2, aA1);
            if (haveB) { efrag(e00, cb + 16, q2, aB0); efrag(e10, cb + 16, q2, aB1); }
        } else {   // XMODE == 2: dir group, aA only
#pragma unroll
            for (int r = 0; r < 4; r++) { aA0[r] = xd0[r]; aA1[r] = xd1[r]; }
        }
        const u32 ga = base + (u32)g * 64u;

        if (XMODE == 0) {
            // V double-buffer: load batch h+1 while mma'ing batch h
            u32 V[2][4][4];
#pragma unroll
            for (int t = 0; t < 4; t++) lds128(V[0][t], ga + (u32)t * (8u * (u32)STB));
#pragma unroll
            for (int h = 0; h < H; h++) {
                if (h + 1 < H) {
#pragma unroll
                    for (int t = 0; t < 4; t++)
                        lds128(V[(h+1)&1][t], ga + (u32)(4*(h+1)+t) * (8u * (u32)STB));
                }
                const u32 (*v)[4] = V[h&1];
#pragma unroll
                for (int t = 0; t < 4; t++) {       // A pass (8 mmas)
                    mma16816(C0[4*h+t], aA0, v[t][0], v[t][1]);
                    mma16816(C1[4*h+t], aA1, v[t][0], v[t][1]);
                }
#pragma unroll
                for (int t = 0; t < 4; t++) {       // B pass (8 mmas)
                    mma16816(C0[4*h+t], aB0, v[t][2], v[t][3]);
                    mma16816(C1[4*h+t], aB1, v[t][2], v[t][3]);
                }
            }
        } else {
#pragma unroll
            for (int h = 0; h < H; h++) {
                u32 V[4][4];
#pragma unroll
                for (int t = 0; t < 4; t++)
                    lds128(V[t], ga + (u32)(4*h+t) * (8u * (u32)STB));
#pragma unroll
                for (int t = 0; t < 4; t++) {       // A pass
                    mma16816(C0[4*h+t], aA0, V[t][0], V[t][1]);
                    mma16816(C1[4*h+t], aA1, V[t][0], V[t][1]);
                }
                if (haveB) {
#pragma unroll
                    for (int t = 0; t < 4; t++) {   // B pass
                        mma16816(C0[4*h+t], aB0, V[t][2], V[t][3]);
                        mma16816(C1[4*h+t], aB1, V[t][2], V[t][3]);
                    }
                }
            }
        }
    }
}

// epilogue: C + bias (+relu) -> f16x2 pack into next-layer A frags
template <bool RELU>
__device__ __forceinline__ void epi_std(float (&C)[16][4], u32 (&AF)[8][4],
                                        const float* bias, int q2)
{
#pragma unroll
    for (int kf = 0; kf < 8; kf++) {
        float2 bA = *(const float2*)(bias + 16 * kf + q2);
        float2 bB = *(const float2*)(bias + 16 * kf + 8 + q2);
        float f0 = C[2*kf][0] + bA.x, f1 = C[2*kf][1] + bA.y;
        float f2 = C[2*kf][2] + bA.x, f3 = C[2*kf][3] + bA.y;
        float g0 = C[2*kf+1][0] + bB.x, g1 = C[2*kf+1][1] + bB.y;
        float g2 = C[2*kf+1][2] + bB.x, g3 = C[2*kf+1][3] + bB.y;
        if (RELU) {
            f0 = fmaxf(f0, 0.f); f1 = fmaxf(f1, 0.f); f2 = fmaxf(f2, 0.f); f3 = fmaxf(f3, 0.f);
            g0 = fmaxf(g0, 0.f); g1 = fmaxf(g1, 0.f); g2 = fmaxf(g2, 0.f); g3 = fmaxf(g3, 0.f);
        }
        AF[kf][0] = pkh(f0, f1); AF[kf][1] = pkh(f2, f3);
        AF[kf][2] = pkh(g0, g1); AF[kf][3] = pkh(g2, g3);
    }
}

// L5 epilogue with fused density head
__device__ __forceinline__ void epi_dens(float (&C)[16][4], u32 (&AF)[8][4],
                                         const float* bias, const float* wcS,
                                         float bd0, float* out, long long base,
                                         int q2, int q, int r0)
{
    float d0 = 0.f, d1 = 0.f;
#pragma unroll
    for (int kf = 0; kf < 8; kf++) {
        float2 bA = *(const float2*)(bias + 16 * kf + q2);
        float2 bB = *(const float2*)(bias + 16 * kf + 8 + q2);
        float2 wA = *(const float2*)(wcS + 16 * kf + q2);
        float2 wB = *(const float2*)(wcS + 16 * kf + 8 + q2);
        float f0 = fmaxf(C[2*kf][0] + bA.x, 0.f), f1 = fmaxf(C[2*kf][1] + bA.y, 0.f);
        float f2 = fmaxf(C[2*kf][2] + bA.x, 0.f), f3 = fmaxf(C[2*kf][3] + bA.y, 0.f);
        float g0 = fmaxf(C[2*kf+1][0] + bB.x, 0.f), g1 = fmaxf(C[2*kf+1][1] + bB.y, 0.f);
        float g2 = fmaxf(C[2*kf+1][2] + bB.x, 0.f), g3 = fmaxf(C[2*kf+1][3] + bB.y, 0.f);
        d0 += f0 * wA.x + f1 * wA.y + g0 * wB.x + g1 * wB.y;
        d1 += f2 * wA.x + f3 * wA.y + g2 * wB.x + g3 * wB.y;
        AF[kf][0] = pkh(f0, f1); AF[kf][1] = pkh(f2, f3);
        AF[kf][2] = pkh(g0, g1); AF[kf][3] = pkh(g2, g3);
    }
    d0 += __shfl_xor_sync(0xffffffffu, d0, 1); d0 += __shfl_xor_sync(0xffffffffu, d0, 2);
    d1 += __shfl_xor_sync(0xffffffffu, d1, 1); d1 += __shfl_xor_sync(0xffffffffu, d1, 2);
    if (q == 0) {
        out[base + r0]     = fmaxf(d0 + bd0, 0.f);
        out[base + r0 + 8] = fmaxf(d1 + bd0, 0.f);
    }
}

// L7 epilogue: relu + rgb head (wr2 + sigmoid)
__device__ __forceinline__ void epi_rgb(float (&C)[16][4], const float* bias,
                                        const float* wr2S, const float* br2S,
                                        float* out, long long obase,
                                        int q2, int q, int r0)
{
    float p00 = 0.f, p01 = 0.f, p02 = 0.f, p10 = 0.f, p11 = 0.f, p12 = 0.f;
#pragma unroll
    for (int nt = 0; nt < 8; nt++) {
        float2 b = *(const float2*)(bias + 8 * nt + q2);
        float f0 = fmaxf(C[nt][0] + b.x, 0.f), f1 = fmaxf(C[nt][1] + b.y, 0.f);
        float f2 = fmaxf(C[nt][2] + b.x, 0.f), f3 = fmaxf(C[nt][3] + b.y, 0.f);
        int p0 = 8 * nt + q2;
        const float* wA = wr2S + p0 * 3;
        const float* wB = wr2S + (p0 + 1) * 3;
        p00 += f0 * wA[0] + f1 * wB[0];
        p01 += f0 * wA[1] + f1 * wB[1];
        p02 += f0 * wA[2] + f1 * wB[2];
        p10 += f2 * wA[0] + f3 * wB[0];
        p11 += f2 * wA[1] + f3 * wB[1];
        p12 += f2 * wA[2] + f3 * wB[2];
    }
    p00 += __shfl_xor_sync(0xffffffffu, p00, 1); p00 += __shfl_xor_sync(0xffffffffu, p00, 2);
    p01 += __shfl_xor_sync(0xffffffffu, p01, 1); p01 += __shfl_xor_sync(0xffffffffu, p01, 2);
    p02 += __shfl_xor_sync(0xffffffffu, p02, 1); p02 += __shfl_xor_sync(0xffffffffu, p02, 2);
    p10 += __shfl_xor_sync(0xffffffffu, p10, 1); p10 += __shfl_xor_sync(0xffffffffu, p10, 2);
    p11 += __shfl_xor_sync(0xffffffffu, p11, 1); p11 += __shfl_xor_sync(0xffffffffu, p11, 2);
    p12 += __shfl_xor_sync(0xffffffffu, p12, 1); p12 += __shfl_xor_sync(0xffffffffu, p12, 2);
    if (q == 0) {
        long long o0 = obase + (long long)r0 * 3;
        long long o1 = obase + (long long)(r0 + 8) * 3;
        out[o0]     = 1.f / (1.f + expf(-(p00 + br2S[0])));
        out[o0 + 1] = 1.f / (1.f + expf(-(p01 + br2S[1])));
        out[o0 + 2] = 1.f / (1.f + expf(-(p02 + br2S[2])));
        out[o1]     = 1.f / (1.f + expf(-(p10 + br2S[0])));
        out[o1 + 1] = 1.f / (1.f + expf(-(p11 + br2S[1])));
        out[o1 + 2] = 1.f / (1.f + expf(-(p12 + br2S[2])));
    }
}

// ---- prep: fp32 W[k][n] -> f16 Wt[n][pos], 32-slot quad-interleaved layout ----
__global__ void prep_kernel(const float* w0, const float* w1, const float* w2, const float* w3,
                            const float* w4, const float* w5, const float* wd, const float* wr1)
{
    const float* srcs[8] = {w0, w1, w2, w3, w4, w5, wd, wr1};
    const int Ksrc[8] = {39, 128, 128, 167, 128, 128, 128, 143};
    const int Kslt[8] = {64, 128, 128, 192, 128, 128, 128, 160};
    const int Nn[8]   = {128, 128, 128, 128, 128, 128, 128, 64};
    const int STw[8]  = {96, 160, 160, 224, 160, 160, 160, 160};
    const int wst[8]  = {128, 128, 128, 128, 128, 128, 129, 64};
    const int cof[8]  = {0, 0, 0, 0, 0, 0, 1, 0};
    const int off[8]  = {0, 24576, 65536, 106496, 163840, 204800, 245760, 286720};
    int j = blockIdx.x;
    const float* src = srcs[j];
    int N = Nn[j], S = STw[j], KS = Kslt[j], tot = N * KS;
    u16* img = (u16*)(g_wimg + off[j]);
    for (int idx = threadIdx.x; idx < tot; idx += blockDim.x) {
        int n = idx / KS, s = idx - n * KS;
        float v = (s < Ksrc[j]) ? __ldg(src + (size_t)s * wst[j] + cof[j] + n) : 0.f;
        int u = s & 31, g32 = s >> 5;
        int q = (u & 7) >> 1;
        int pos = g32 * 32 + q * 8 + ((u >> 4) & 1) * 4 + ((u >> 3) & 1) * 2 + (u & 1);
        img[(size_t)n * S + pos] = __half_as_ushort(__float2half_rn(v));
    }
}

__global__ void __launch_bounds__(NTHR, 1) nerf_mma_kernel(
    const float* __restrict__ pts, const float* __restrict__ dirs,
    const float* __restrict__ b0, const float* __restrict__ b1,
    const float* __restrict__ b2, const float* __restrict__ b3,
    const float* __restrict__ b4, const float* __restrict__ b5,
    const float* __restrict__ bd, const float* __restrict__ br1,
    const float* __restrict__ wd, const float* __restrict__ wr2,
    const float* __restrict__ br2, float* __restrict__ out, int ntiles)
{
    extern __shared__ __align__(16) unsigned char sm[];
    unsigned char* wbuf0 = sm;                       // 40960
    unsigned char* wbuf1 = sm + 40960;               // 57344
    float* esm  = (float*)(sm + 98304);              // 256 x ES fp32 embed (2 tiles)
    float* aux  = (float*)(sm + 98304 + 256 * ES * 4);
    float* biasS = aux;                              // 8 x 128
    float* wcS   = aux + 1024;                       // wd col 0
    float* wr2S  = aux + 1152;                       // 64 x 3
    float* br2S  = aux + 1344;                       // 3
    const u32 wb0 = smaddr(wbuf0), wb1 = smaddr(wbuf1);

    const int tid = threadIdx.x, lane = tid & 31, wid = tid >> 5;
    const int q  = lane & 3;
    const int q2 = 2 * q;
    const int r0 = 16 * wid + (lane >> 2);
    const int nl = lane >> 2;

    {
        const float* bp[8] = {b0, b1, b2, b3, b4, b5, bd + 1, br1};
#pragma unroll 1
        for (int l = 0; l < 8; l++) {
            int n = (l == 7) ? 64 : 128;
            for (int i = tid; i < n; i += NTHR) biasS[l * 128 + i] = __ldg(bp[l] + i);
        }
        for (int i = tid; i < 128; i += NTHR) wcS[i] = __ldg(wd + (size_t)i * 129);
        for (int i = tid; i < 192; i += NTHR) wr2S[i] = __ldg(wr2 + i);
        if (tid < 3) br2S[tid] = __ldg(br2 + tid);
        for (int i = tid; i < 256 * ES; i += NTHR) esm[i] = 0.f;
    }
    copy_async(wb0, g_wimg, 24576, tid);   // L0
    CPW();
    __syncthreads();

    float C0[16][4], C1[16][4];
    u32 AF0[8][4], AF1[8][4];
    const float bd0 = __ldg(bd);
    const long long NPTS = (long long)ntiles * 128;
    const int npairs = ntiles >> 1;

    const u32 t192 = (u32)(nl * 192 + q * 16);
    const u32 t320 = (u32)(nl * 320 + q * 16);
    const u32 t448 = (u32)(nl * 448 + q * 16);
    const float* e00 = esm + r0 * ES;
    const float* e10 = esm + (128 + r0) * ES;

    for (int pair = blockIdx.x; pair < npairs; pair += gridDim.x) {
        // ---- xyz harmonic embed for BOTH tiles (2 threads per point, 2 passes) ----
#pragma unroll 1
        for (int p2 = 0; p2 < 2; p2++) {
            int p = tid & 127, half = tid >> 7;
            const float* qp = pts + (((long long)(2 * pair + p2)) * 128 + p) * 3;
            float v0 = __ldg(qp), v1 = __ldg(qp + 1), v2 = __ldg(qp + 2);
            float* er = esm + (p2 * 128 + p) * ES;
            if (half == 0) {
                float fr = 1.f;
#pragma unroll
                for (int f = 0; f < 6; f++) {
                    float s, c; sincosf(v0 * fr, &s, &c);
                    er[f] = s; er[18 + f] = c; fr *= 2.f;
                }
                fr = 1.f;
#pragma unroll
                for (int f = 0; f < 3; f++) {
                    float s, c; sincosf(v2 * fr, &s, &c);
                    er[12 + f] = s; er[30 + f] = c; fr *= 2.f;
                }
                er[36] = v0; er[37] = v1; er[38] = v2;
            } else {
                float fr = 1.f;
#pragma unroll
                for (int f = 0; f < 6; f++) {
                    float s, c; sincosf(v1 * fr, &s, &c);
                    er[6 + f] = s; er[24 + f] = c; fr *= 2.f;
                }
                fr = 8.f;
#pragma unroll
                for (int f = 3; f < 6; f++) {
                    float s, c; sincosf(v2 * fr, &s, &c);
                    er[12 + f] = s; er[30 + f] = c; fr *= 2.f;
                }
            }
        }
        __syncthreads();

        // ---- L0 (xyz from esm, 2 extra groups, last kf skipped) ----
        copy_async(wb1, g_wimg + 24576, 40960, tid);
        gemm_dual<0, 1, 16, 192>(C0, C1, AF0, AF1, wb0 + t192, e00, e10, 0, 0, q2);
        epi_std<true>(C0, AF0, biasS, q2);
        epi_std<true>(C1, AF1, biasS, q2);
        CPW(); __syncthreads();

        // ---- L1 ----
        copy_async(wb0, g_wimg + 65536, 40960, tid);
        gemm_dual<4, 0, 16, 320>(C0, C1, AF0, AF1, wb1 + t320, 0, 0, 0, 0, q2);
        epi_std<true>(C0, AF0, biasS + 128, q2);
        epi_std<true>(C1, AF1, biasS + 128, q2);
        CPW(); __syncthreads();

        // ---- L2 ----
        copy_async(wb1, g_wimg + 106496, 57344, tid);
        gemm_dual<4, 0, 16, 320>(C0, C1, AF0, AF1, wb0 + t320, 0, 0, 0, 0, q2);
        epi_std<true>(C0, AF0, biasS + 256, q2);
        epi_std<true>(C1, AF1, biasS + 256, q2);
        CPW(); __syncthreads();

        // ---- L3 (skip concat: 4 AF groups + 2 esm groups) ----
        copy_async(wb0, g_wimg + 163840, 40960, tid);
        gemm_dual<4, 1, 16, 448>(C0, C1, AF0, AF1, wb1 + t448, e00, e10, 0, 0, q2);
        epi_std<true>(C0, AF0, biasS + 384, q2);
        epi_std<true>(C1, AF1, biasS + 384, q2);
        CPW(); __syncthreads();

        // ---- L4 ----
        copy_async(wb1, g_wimg + 204800, 40960, tid);
        gemm_dual<4, 0, 16, 320>(C0, C1, AF0, AF1, wb0 + t320, 0, 0, 0, 0, q2);
        epi_std<true>(C0, AF0, biasS + 512, q2);
        epi_std<true>(C1, AF1, biasS + 512, q2);
        CPW(); __syncthreads();

        // ---- L5 (+fused density heads) ----
        copy_async(wb0, g_wimg + 245760, 40960, tid);
        gemm_dual<4, 0, 16, 320>(C0, C1, AF0, AF1, wb1 + t320, 0, 0, 0, 0, q2);
        {
            long long base0 = (long long)(2 * pair) * 128;
            epi_dens(C0, AF0, biasS + 640, wcS, bd0, out, base0,       q2, q, r0);
            epi_dens(C1, AF1, biasS + 640, wcS, bd0, out, base0 + 128, q2, q, r0);
        }
        CPW(); __syncthreads();

        // ---- L6 (wd cols 1..128, NO relu) ----
        copy_async(wb1, g_wimg + 286720, 20480, tid);
        gemm_dual<4, 0, 16, 320>(C0, C1, AF0, AF1, wb0 + t320, 0, 0, 0, 0, q2);
        epi_std<false>(C0, AF0, biasS + 768, q2);
        epi_std<false>(C1, AF1, biasS + 768, q2);
        CPW(); __syncthreads();

        // ---- dir frags for both tiles (4 regs each) ----
        u32 xd0[4], xd1[4];
#pragma unroll 1
        for (int p2 = 0; p2 < 2; p2++) {
            const float* dp = dirs + (long long)(2 * pair + p2) * 3;
            float d[16];
#pragma unroll
            for (int c = 0; c < 3; c++) {
                float v = __ldg(dp + c);
                float s0, cc0, s1, cc1;
                sincosf(v, &s0, &cc0); sincosf(2.f * v, &s1, &cc1);
                d[2*c] = s0; d[2*c+1] = s1; d[6+2*c] = cc0; d[7+2*c] = cc1; d[12+c] = v;
            }
            d[15] = 0.f;
            u32 lo = pkh(d[q2], d[q2+1]);
            u32 hi = pkh(d[8+q2], d[9+q2]);
            u32* xd = (p2 == 0) ? xd0 : xd1;
            xd[0] = lo; xd[1] = lo; xd[2] = hi; xd[3] = hi;
        }

        // ---- L7 (wr1 -> 64: 4 AF groups + dir group (aA only), +fused rgb heads) ----
        copy_async(wb0, g_wimg, 24576, tid);   // next pair's L0
        gemm_dual<4, 2, 8, 320>(C0, C1, AF0, AF1, wb1 + t320, 0, 0, xd0, xd1, q2);
        {
            long long pb0 = (long long)(2 * pair) * 128;
            epi_rgb(C0, biasS + 896, wr2S, br2S, out, NPTS + pb0 * 3,         q2, q, r0);
            epi_rgb(C1, biasS + 896, wr2S, br2S, out, NPTS + (pb0 + 128) * 3, q2, q, r0);
        }
        CPW(); __syncthreads();
    }
}

extern "C" void kernel_launch(void* const* d_in, const int* in_sizes, int n_in,
                              void* d_out, int out_size)
{
    const float* pts  = (const float*)d_in[0];
    const float* dirs = (const float*)d_in[1];
    const float *w0 = (const float*)d_in[2],  *b0 = (const float*)d_in[3];
    const float *w1 = (const float*)d_in[4],  *b1 = (const float*)d_in[5];
    const float *w2 = (const float*)d_in[6],  *b2 = (const float*)d_in[7];
    const float *w3 = (const float*)d_in[8],  *b3 = (const float*)d_in[9];
    const float *w4 = (const float*)d_in[10], *b4 = (const float*)d_in[11];
    const float *w5 = (const float*)d_in[12], *b5 = (const float*)d_in[13];
    const float *wd = (const float*)d_in[14], *bd = (const float*)d_in[15];
    const float *wr1 = (const float*)d_in[16], *br1 = (const float*)d_in[17];
    const float *wr2 = (const float*)d_in[18], *br2 = (const float*)d_in[19];
    float* out = (float*)d_out;

    int ntiles = in_sizes[1] / 3;   // rays
    int npairs = ntiles >> 1;
    int nsm = 0;
    cudaDeviceGetAttribute(&nsm, cudaDevAttrMultiProcessorCount, 0);
    if (nsm <= 0) nsm = 148;
    int grid = nsm < npairs ? nsm : npairs;

    size_t smem = 98304 + 256 * ES * 4 + 5392;   // ~173 KB
    cudaFuncSetAttribute(nerf_mma_kernel, cudaFuncAttributeMaxDynamicSharedMemorySize, (int)smem);

    prep_kernel<<<8, 512>>>(w0, w1, w2, w3, w4, w5, wd, wr1);
    nerf_mma_kernel<<<grid, NTHR, smem>>>(pts, dirs, b0, b1, b2, b3, b4, b5,
                                          bd, br1, wd, wr2, br2, out, ntiles);
}